// round 7
// baseline (speedup 1.0000x reference)
#include <cuda_runtime.h>
#include <cuda_bf16.h>
#include <math.h>
#include <stdint.h>

#define BATCH 16384
#define DIN   512
#define HDIM  256
#define NTILES 3072      // 128 m-blocks * 12 z * 2 n-tiles
#define GRIDP  296       // 2 CTAs per SM * 148 SMs

// -------- scratch (static device allocations; no cudaMalloc allowed) --------
__device__ float g_spec[8 * BATCH * HDIM];            // [z][b][h]
__device__ float g_shared[4 * BATCH * HDIM];          // [e][b][h]
__device__ float g_gw[4 * BATCH * 6];                 // FINAL domain gate weights
__device__ float g_gsw[BATCH * 12];                   // FINAL shared gate weights
__device__ __nv_bfloat16 g_xhi[5 * BATCH * DIN];
__device__ __nv_bfloat16 g_xlo[5 * BATCH * DIN];
__device__ __nv_bfloat16 g_whi[12 * DIN * HDIM];      // [z][k][n]
__device__ __nv_bfloat16 g_wlo[12 * DIN * HDIM];

// ============================================================================
// helpers (family-common PTX only: cp.async / ldmatrix / mma.sync)
// ============================================================================
__device__ __forceinline__ uint32_t smem_u32(const void* p) {
    uint32_t a;
    asm("{ .reg .u64 t; cvta.to.shared.u64 t, %1; cvt.u32.u64 %0, t; }" : "=r"(a) : "l"(p));
    return a;
}
__device__ __forceinline__ void cpasync16(uint32_t dst, const void* src) {
    asm volatile("cp.async.cg.shared.global [%0], [%1], 16;" :: "r"(dst), "l"(src) : "memory");
}
#define CP_COMMIT() asm volatile("cp.async.commit_group;" ::: "memory")
#define CP_WAIT1()  asm volatile("cp.async.wait_group 1;" ::: "memory")

__device__ __forceinline__ void ldsm4(uint32_t& r0, uint32_t& r1, uint32_t& r2, uint32_t& r3, uint32_t addr) {
    asm volatile("ldmatrix.sync.aligned.m8n8.x4.shared.b16 {%0,%1,%2,%3}, [%4];"
                 : "=r"(r0), "=r"(r1), "=r"(r2), "=r"(r3) : "r"(addr));
}
__device__ __forceinline__ void ldsm4t(uint32_t& r0, uint32_t& r1, uint32_t& r2, uint32_t& r3, uint32_t addr) {
    asm volatile("ldmatrix.sync.aligned.m8n8.x4.trans.shared.b16 {%0,%1,%2,%3}, [%4];"
                 : "=r"(r0), "=r"(r1), "=r"(r2), "=r"(r3) : "r"(addr));
}
__device__ __forceinline__ void mma16816(float* d, const uint32_t* a, uint32_t b0, uint32_t b1) {
    asm volatile(
        "mma.sync.aligned.m16n8k16.row.col.f32.bf16.bf16.f32 "
        "{%0,%1,%2,%3}, {%4,%5,%6,%7}, {%8,%9}, {%0,%1,%2,%3};"
        : "+f"(d[0]), "+f"(d[1]), "+f"(d[2]), "+f"(d[3])
        : "r"(a[0]), "r"(a[1]), "r"(a[2]), "r"(a[3]), "r"(b0), "r"(b1));
}

__device__ __forceinline__ void split2(float a0, float a1, uint32_t& hi, uint32_t& lo) {
    __nv_bfloat16 h0 = __float2bfloat16(a0);
    __nv_bfloat16 h1 = __float2bfloat16(a1);
    __nv_bfloat16 l0 = __float2bfloat16(a0 - __bfloat162float(h0));
    __nv_bfloat16 l1 = __float2bfloat16(a1 - __bfloat162float(h1));
    hi = ((uint32_t)__bfloat16_as_ushort(h1) << 16) | __bfloat16_as_ushort(h0);
    lo = ((uint32_t)__bfloat16_as_ushort(l1) << 16) | __bfloat16_as_ushort(l0);
}

// ============================================================================
// Fused gates + split kernel.
// Blocks [0, NGATE): gate logits + both softmaxes + sim mask (final weights).
//   These are latency-heavy and go FIRST so they overlap the split wave.
// Blocks [NGATE, NGATE+NSPLIT4): f32 -> bf16 hi/lo split, 4 float4/thread
//   with all 4 loads issued independently (MLP=4).
// ============================================================================
#define NX4  (5 * BATCH * DIN / 4)          // 10485760
#define NWS4 (8 * DIN * HDIM / 4)           // 262144
#define NWH4 (4 * DIN * HDIM / 4)           // 131072
#define NTOT4 (NX4 + NWS4 + NWH4)           // 10878976
#define NSPLIT4 (NTOT4 / 1024)              // 10624 blocks (256 thr * 4 f4)
#define NGATE  (BATCH / 8)                  // 2048

__global__ __launch_bounds__(256)
void split_gates_kernel(const float4* __restrict__ x,
                        const float4* __restrict__ Ws,
                        const float4* __restrict__ Wh,
                        const float* __restrict__ Wg,  const float* __restrict__ bg,
                        const float* __restrict__ Wgs, const float* __restrict__ bgs,
                        const int* __restrict__ sim)
{
    if (blockIdx.x >= NGATE) {
        // ---- split path: 4 independent float4s per thread ----
        const size_t base = (size_t)(blockIdx.x - NGATE) * 1024 + threadIdx.x;
        float4 v[4];
        size_t off[4];
        bool isx[4];
#pragma unroll
        for (int j = 0; j < 4; ++j) {
            const size_t i = base + j * 256;
            if (i < NX4) { off[j] = i; isx[j] = true;  v[j] = x[i]; }
            else {
                const size_t o = i - NX4;
                off[j] = o; isx[j] = false;
                v[j] = (o < NWS4) ? Ws[o] : Wh[o - NWS4];
            }
        }
#pragma unroll
        for (int j = 0; j < 4; ++j) {
            uint32_t h01, l01, h23, l23;
            split2(v[j].x, v[j].y, h01, l01);
            split2(v[j].z, v[j].w, h23, l23);
            uint2* dh = isx[j] ? (uint2*)g_xhi : (uint2*)g_whi;
            uint2* dl = isx[j] ? (uint2*)g_xlo : (uint2*)g_wlo;
            dh[off[j]] = make_uint2(h01, h23);
            dl[off[j]] = make_uint2(l01, l23);
        }
        return;
    }

    // ---- gates path ----
    const float* xf = (const float*)x;
    const int b    = blockIdx.x * 8 + (threadIdx.x >> 5);
    const int lane = threadIdx.x & 31;

#pragma unroll
    for (int n = 0; n < 4; ++n) {
        const float* xr = xf + ((size_t)n * BATCH + b) * DIN;
        float xv[16];
#pragma unroll
        for (int i = 0; i < 16; ++i) xv[i] = xr[lane + 32 * i];
        float zz[6];
#pragma unroll
        for (int e = 0; e < 6; ++e) {
            float acc = 0.f;
#pragma unroll
            for (int i = 0; i < 16; ++i)
                acc = fmaf(xv[i], Wg[(size_t)n * DIN * 6 + (size_t)(lane + 32 * i) * 6 + e], acc);
#pragma unroll
            for (int o = 16; o; o >>= 1) acc += __shfl_xor_sync(0xffffffffu, acc, o);
            zz[e] = acc + bg[n * 6 + e];
        }
        float m1 = zz[0];
#pragma unroll
        for (int e = 1; e < 6; ++e) m1 = fmaxf(m1, zz[e]);
        float s1 = 0.f;
#pragma unroll
        for (int e = 0; e < 6; ++e) { zz[e] = __expf(zz[e] - m1); s1 += zz[e]; }
        const float inv1 = 1.f / s1;
#pragma unroll
        for (int e = 0; e < 6; ++e) zz[e] *= inv1;

        const int s0 = sim[n * 2], s1i = sim[n * 2 + 1];
        bool valid[6];
        valid[0] = true; valid[1] = true;
#pragma unroll
        for (int e = 0; e < 4; ++e) valid[2 + e] = (s0 == e) || (s1i == e);
        float m2 = -1e30f;
#pragma unroll
        for (int e = 0; e < 6; ++e) if (valid[e]) m2 = fmaxf(m2, zz[e]);
        float w[6]; float s2 = 0.f;
#pragma unroll
        for (int e = 0; e < 6; ++e) { w[e] = valid[e] ? __expf(zz[e] - m2) : 0.f; s2 += w[e]; }
        const float inv2 = 1.f / s2;
        if (lane == 0) {
#pragma unroll
            for (int e = 0; e < 6; ++e)
                g_gw[((size_t)n * BATCH + b) * 6 + e] = w[e] * inv2;
        }
    }
    {
        const float* xr = xf + ((size_t)4 * BATCH + b) * DIN;
        float xv[16];
#pragma unroll
        for (int i = 0; i < 16; ++i) xv[i] = xr[lane + 32 * i];
        float gs[12];
#pragma unroll
        for (int e = 0; e < 12; ++e) {
            float acc = 0.f;
#pragma unroll
            for (int i = 0; i < 16; ++i)
                acc = fmaf(xv[i], Wgs[(size_t)(lane + 32 * i) * 12 + e], acc);
#pragma unroll
            for (int o = 16; o; o >>= 1) acc += __shfl_xor_sync(0xffffffffu, acc, o);
            gs[e] = acc + bgs[e];
        }
        float m = gs[0];
#pragma unroll
        for (int e = 1; e < 12; ++e) m = fmaxf(m, gs[e]);
        float s = 0.f;
#pragma unroll
        for (int e = 0; e < 12; ++e) { gs[e] = __expf(gs[e] - m); s += gs[e]; }
        const float inv = 1.f / s;
        if (lane == 0) {
#pragma unroll
            for (int e = 0; e < 12; ++e)
                g_gsw[(size_t)b * 12 + e] = gs[e] * inv;
        }
    }
}

// ============================================================================
// Persistent tensor-core GEMM (mma.sync bf16, 3-product split).
// Tile order t = (m*12 + z)*2 + nt  (z inner -> concurrent CTAs share the same
// m-block of A; W stays L2-resident). One continuous 3-stage cp.async ring
// across tile boundaries; epilogue is reg->global only and overlaps loads.
// ============================================================================
#define OFF_AHI 0
#define OFF_ALO 10240
#define OFF_BHI 20480
#define OFF_BLO 28672
#define STG     36864
#define GEMM_SMEM (3 * STG)   // 110592

__device__ __forceinline__ void issue_stage(uint32_t sm32, int buf, int tile, int kt, int tid)
{
    const int nt   = tile & 1;
    const int z    = (tile >> 1) % 12;
    const int mblk = tile / 24;
    const int m0 = mblk * 128, n0 = nt * 128, c0 = kt * 32;
    const int zsel = (z < 8) ? (z >> 1) : 4;
    const __nv_bfloat16* xhi = g_xhi + (size_t)zsel * BATCH * DIN;
    const __nv_bfloat16* xlo = g_xlo + (size_t)zsel * BATCH * DIN;
    const __nv_bfloat16* whi = g_whi + (size_t)z * DIN * HDIM;
    const __nv_bfloat16* wlo = g_wlo + (size_t)z * DIN * HDIM;

    const uint32_t sa = sm32 + buf * STG;
    // A: 128 rows x 32k hi/lo, padded rows (80B)
#pragma unroll
    for (int i = 0; i < 2; ++i) {
        const int idx = tid + i * 256;
        const int m = idx >> 2, u = idx & 3;
        const size_t go = (size_t)(m0 + m) * DIN + c0 + u * 8;
        const uint32_t d = sa + OFF_AHI + m * 80 + u * 16;
        cpasync16(d, xhi + go);
        cpasync16(d + (OFF_ALO - OFF_AHI), xlo + go);
    }
    // B: 32 k-rows x 128n hi/lo, XOR-swizzled 16B units
#pragma unroll
    for (int i = 0; i < 2; ++i) {
        const int idx = tid + i * 256;
        const int k = idx >> 4, u = idx & 15;
        const size_t go = (size_t)(c0 + k) * HDIM + n0 + u * 8;
        const uint32_t phys = (u & 8) | ((u & 7) ^ (k & 7));
        const uint32_t d = sa + OFF_BHI + k * 256 + phys * 16;
        cpasync16(d, whi + go);
        cpasync16(d + (OFF_BLO - OFF_BHI), wlo + go);
    }
}

__global__ void __launch_bounds__(256, 2)
gemm_tc(const float* __restrict__ bspec, const float* __restrict__ bsh)
{
    extern __shared__ char smem[];
    const uint32_t sm32 = smem_u32(smem);
    const int tid  = threadIdx.x;
    const int wid  = tid >> 5;
    const int lane = tid & 31;
    const int wm0  = (wid & 3) * 32;
    const int wn0  = (wid >> 2) * 64;

    const int cnt   = (NTILES - blockIdx.x + GRIDP - 1) / GRIDP;
    const int total = cnt * 16;

    float acc[2][8][4];
#pragma unroll
    for (int f = 0; f < 2; ++f)
#pragma unroll
        for (int j = 0; j < 8; ++j)
#pragma unroll
            for (int q = 0; q < 4; ++q) acc[f][j][q] = 0.f;

    // prologue: 2 stages in flight
    issue_stage(sm32, 0, blockIdx.x, 0, tid); CP_COMMIT();
    issue_stage(sm32, 1, blockIdx.x, 1, tid); CP_COMMIT();

    for (int ls = 0; ls < total; ++ls) {
        CP_WAIT1();
        __syncthreads();

        const int ls2 = ls + 2;
        if (ls2 < total)
            issue_stage(sm32, ls2 % 3, blockIdx.x + (ls2 >> 4) * GRIDP, ls2 & 15, tid);
        CP_COMMIT();   // empty group at tail keeps wait accounting consistent

        const uint32_t sa = sm32 + (ls % 3) * STG;
#pragma unroll
        for (int ksb = 0; ksb < 2; ++ksb) {
            const int kb = ksb * 16;
            uint32_t ah[2][4], al[2][4];
#pragma unroll
            for (int f = 0; f < 2; ++f) {
                const uint32_t aaddr = sa + OFF_AHI
                    + (wm0 + f * 16 + (lane & 15)) * 80
                    + (kb + ((lane >> 4) << 3)) * 2;
                ldsm4(ah[f][0], ah[f][1], ah[f][2], ah[f][3], aaddr);
                ldsm4(al[f][0], al[f][1], al[f][2], al[f][3], aaddr + (OFF_ALO - OFF_AHI));
            }
            const int g = lane >> 3, r = lane & 7;
            const int krow = kb + (g & 1) * 8 + r;
#pragma unroll
            for (int c = 0; c < 4; ++c) {
                const int noff = wn0 + c * 16 + (g >> 1) * 8;
                const uint32_t u = (uint32_t)(noff >> 3);
                const uint32_t phys = (u & 8) | ((u & 7) ^ (uint32_t)(krow & 7));
                const uint32_t baddr = sa + OFF_BHI + krow * 256 + phys * 16;
                uint32_t bh[4], bl[4];
                ldsm4t(bh[0], bh[1], bh[2], bh[3], baddr);
                ldsm4t(bl[0], bl[1], bl[2], bl[3], baddr + (OFF_BLO - OFF_BHI));
#pragma unroll
                for (int f = 0; f < 2; ++f) {
#pragma unroll
                    for (int jj = 0; jj < 2; ++jj) {
                        float* d = acc[f][2 * c + jj];
                        mma16816(d, ah[f], bh[2 * jj], bh[2 * jj + 1]);
                        mma16816(d, ah[f], bl[2 * jj], bl[2 * jj + 1]);
                        mma16816(d, al[f], bh[2 * jj], bh[2 * jj + 1]);
                    }
                }
            }
        }

        if ((ls & 15) == 15) {
            // tile epilogue: reg -> global only (no smem), overlaps next loads
            const int tile = blockIdx.x + (ls >> 4) * GRIDP;
            const int nt   = tile & 1;
            const int z    = (tile >> 1) % 12;
            const int mblk = tile / 24;
            const int m0 = mblk * 128, n0 = nt * 128;
            const float* bias = (z < 8) ? (bspec + z * HDIM) : (bsh + (z - 8) * HDIM);
            float* outp = (z < 8) ? (g_spec + (size_t)z * BATCH * HDIM)
                                  : (g_shared + (size_t)(z - 8) * BATCH * HDIM);
#pragma unroll
            for (int f = 0; f < 2; ++f) {
#pragma unroll
                for (int j = 0; j < 8; ++j) {
                    const int row = m0 + wm0 + f * 16 + (lane >> 2);
                    const int col = n0 + wn0 + j * 8 + (lane & 3) * 2;
                    const float b0 = __ldg(&bias[col]);
                    const float b1 = __ldg(&bias[col + 1]);
                    float2 v0, v1;
                    v0.x = fmaxf(acc[f][j][0] + b0, 0.f);
                    v0.y = fmaxf(acc[f][j][1] + b1, 0.f);
                    v1.x = fmaxf(acc[f][j][2] + b0, 0.f);
                    v1.y = fmaxf(acc[f][j][3] + b1, 0.f);
                    *(float2*)(outp + (size_t)row * HDIM + col)       = v0;
                    *(float2*)(outp + (size_t)(row + 8) * HDIM + col) = v1;
#pragma unroll
                    for (int q = 0; q < 4; ++q) acc[f][j][q] = 0.f;
                }
            }
        }
    }
}

// ============================================================================
// Combine: 4 rows per block, float4 per thread, zero transcendentals.
// ============================================================================
__global__ __launch_bounds__(256)
void combine_kernel(float* __restrict__ out)
{
    __shared__ float w[4][36];
    const int b0  = blockIdx.x * 4;
    const int tid = threadIdx.x;
    if (tid < 144) {
        const int row = tid / 36, e = tid % 36;
        float v;
        if (e < 24) v = g_gw[((size_t)(e / 6) * BATCH + b0 + row) * 6 + (e % 6)];
        else        v = g_gsw[(size_t)(b0 + row) * 12 + (e - 24)];
        w[row][e] = v;
    }
    __syncthreads();

    const int r = tid >> 6;
    const int b = b0 + r;
    const int h = (tid & 63) * 4;

    float4 sp[8];
#pragma unroll
    for (int j = 0; j < 8; ++j)
        sp[j] = *(const float4*)&g_spec[((size_t)j * BATCH + b) * HDIM + h];
    float4 sh[4];
#pragma unroll
    for (int e = 0; e < 4; ++e)
        sh[e] = *(const float4*)&g_shared[((size_t)e * BATCH + b) * HDIM + h];

    // shared-gate output
    {
        float4 o = make_float4(0.f, 0.f, 0.f, 0.f);
#pragma unroll
        for (int j = 0; j < 8; ++j) {
            const float ww = w[r][24 + j];
            o.x = fmaf(ww, sp[j].x, o.x); o.y = fmaf(ww, sp[j].y, o.y);
            o.z = fmaf(ww, sp[j].z, o.z); o.w = fmaf(ww, sp[j].w, o.w);
        }
#pragma unroll
        for (int e = 0; e < 4; ++e) {
            const float ww = w[r][32 + e];
            o.x = fmaf(ww, sh[e].x, o.x); o.y = fmaf(ww, sh[e].y, o.y);
            o.z = fmaf(ww, sh[e].z, o.z); o.w = fmaf(ww, sh[e].w, o.w);
        }
        *(float4*)&out[((size_t)4 * BATCH + b) * HDIM + h] = o;
    }

    // per-domain outputs
#pragma unroll
    for (int n = 0; n < 4; ++n) {
        float4 o = make_float4(0.f, 0.f, 0.f, 0.f);
        const float w0 = w[r][n * 6 + 0], w1 = w[r][n * 6 + 1];
        o.x = w0 * sp[2 * n].x + w1 * sp[2 * n + 1].x;
        o.y = w0 * sp[2 * n].y + w1 * sp[2 * n + 1].y;
        o.z = w0 * sp[2 * n].z + w1 * sp[2 * n + 1].z;
        o.w = w0 * sp[2 * n].w + w1 * sp[2 * n + 1].w;
#pragma unroll
        for (int e = 0; e < 4; ++e) {
            const float ww = w[r][n * 6 + 2 + e];
            o.x = fmaf(ww, sh[e].x, o.x); o.y = fmaf(ww, sh[e].y, o.y);
            o.z = fmaf(ww, sh[e].z, o.z); o.w = fmaf(ww, sh[e].w, o.w);
        }
        *(float4*)&out[((size_t)n * BATCH + b) * HDIM + h] = o;
    }
}

// ============================================================================
extern "C" void kernel_launch(void* const* d_in, const int* in_sizes, int n_in,
                              void* d_out, int out_size)
{
    const float* x     = (const float*)d_in[0];
    const int*   sim   = (const int*)d_in[1];
    const float* Wspec = (const float*)d_in[2];
    const float* bspec = (const float*)d_in[3];
    const float* Wsh   = (const float*)d_in[4];
    const float* bsh   = (const float*)d_in[5];
    const float* Wg    = (const float*)d_in[6];
    const float* bg    = (const float*)d_in[7];
    const float* Wgs   = (const float*)d_in[8];
    const float* bgs   = (const float*)d_in[9];
    float* out = (float*)d_out;

    split_gates_kernel<<<NGATE + NSPLIT4, 256>>>(
        (const float4*)x, (const float4*)Wspec, (const float4*)Wsh,
        Wg, bg, Wgs, bgs, sim);

    cudaFuncSetAttribute(gemm_tc, cudaFuncAttributeMaxDynamicSharedMemorySize, GEMM_SMEM);
    gemm_tc<<<GRIDP, 256, GEMM_SMEM>>>(bspec, bsh);

    combine_kernel<<<BATCH / 4, 256>>>(out);
}

// round 8
// speedup vs baseline: 1.4480x; 1.4480x over previous
#include <cuda_runtime.h>
#include <cuda_bf16.h>
#include <math.h>
#include <stdint.h>

#define BATCH 16384
#define DIN   512
#define HDIM  256
#define NTILES 3072      // 128 m-blocks * 12 z * 2 n-tiles
#define GRIDP  296       // 2 CTAs per SM * 148 SMs

// -------- scratch (static device allocations; no cudaMalloc allowed) --------
__device__ float g_spec[8 * BATCH * HDIM];            // [z][b][h]
__device__ float g_shared[4 * BATCH * HDIM];          // [e][b][h]
__device__ float g_gw[4 * BATCH * 6];                 // FINAL domain gate weights
__device__ float g_gsw[BATCH * 12];                   // FINAL shared gate weights
__device__ __nv_bfloat16 g_xhi[5 * BATCH * DIN];
__device__ __nv_bfloat16 g_xlo[5 * BATCH * DIN];
__device__ __nv_bfloat16 g_whi[12 * DIN * HDIM];      // [z][k][n]
__device__ __nv_bfloat16 g_wlo[12 * DIN * HDIM];

// ============================================================================
// helpers (family-common PTX only: cp.async / ldmatrix / mma.sync)
// ============================================================================
__device__ __forceinline__ uint32_t smem_u32(const void* p) {
    uint32_t a;
    asm("{ .reg .u64 t; cvta.to.shared.u64 t, %1; cvt.u32.u64 %0, t; }" : "=r"(a) : "l"(p));
    return a;
}
__device__ __forceinline__ void cpasync16(uint32_t dst, const void* src) {
    asm volatile("cp.async.cg.shared.global [%0], [%1], 16;" :: "r"(dst), "l"(src) : "memory");
}
#define CP_COMMIT() asm volatile("cp.async.commit_group;" ::: "memory")
#define CP_WAIT1()  asm volatile("cp.async.wait_group 1;" ::: "memory")

__device__ __forceinline__ void ldsm4(uint32_t& r0, uint32_t& r1, uint32_t& r2, uint32_t& r3, uint32_t addr) {
    asm volatile("ldmatrix.sync.aligned.m8n8.x4.shared.b16 {%0,%1,%2,%3}, [%4];"
                 : "=r"(r0), "=r"(r1), "=r"(r2), "=r"(r3) : "r"(addr));
}
__device__ __forceinline__ void ldsm4t(uint32_t& r0, uint32_t& r1, uint32_t& r2, uint32_t& r3, uint32_t addr) {
    asm volatile("ldmatrix.sync.aligned.m8n8.x4.trans.shared.b16 {%0,%1,%2,%3}, [%4];"
                 : "=r"(r0), "=r"(r1), "=r"(r2), "=r"(r3) : "r"(addr));
}
__device__ __forceinline__ void mma16816(float* d, const uint32_t* a, uint32_t b0, uint32_t b1) {
    asm volatile(
        "mma.sync.aligned.m16n8k16.row.col.f32.bf16.bf16.f32 "
        "{%0,%1,%2,%3}, {%4,%5,%6,%7}, {%8,%9}, {%0,%1,%2,%3};"
        : "+f"(d[0]), "+f"(d[1]), "+f"(d[2]), "+f"(d[3])
        : "r"(a[0]), "r"(a[1]), "r"(a[2]), "r"(a[3]), "r"(b0), "r"(b1));
}

__device__ __forceinline__ void split2(float a0, float a1, uint32_t& hi, uint32_t& lo) {
    __nv_bfloat16 h0 = __float2bfloat16(a0);
    __nv_bfloat16 h1 = __float2bfloat16(a1);
    __nv_bfloat16 l0 = __float2bfloat16(a0 - __bfloat162float(h0));
    __nv_bfloat16 l1 = __float2bfloat16(a1 - __bfloat162float(h1));
    hi = ((uint32_t)__bfloat16_as_ushort(h1) << 16) | __bfloat16_as_ushort(h0);
    lo = ((uint32_t)__bfloat16_as_ushort(l1) << 16) | __bfloat16_as_ushort(l0);
}

// ============================================================================
// Split kernel (R5-proven form): one float4 per thread.
// ============================================================================
#define NX4  (5 * BATCH * DIN / 4)
#define NWS4 (8 * DIN * HDIM / 4)
#define NWH4 (4 * DIN * HDIM / 4)
#define NSPLIT_BLOCKS ((NX4 + NWS4 + NWH4) / 256)

__global__ __launch_bounds__(256)
void split_kernel(const float4* __restrict__ x,
                  const float4* __restrict__ Ws,
                  const float4* __restrict__ Wh)
{
    const size_t i = (size_t)blockIdx.x * 256 + threadIdx.x;
    float4 v; uint2* dh; uint2* dl; size_t off;
    if (i < NX4) {
        off = i;  v = x[off];
        dh = (uint2*)g_xhi; dl = (uint2*)g_xlo;
    } else {
        off = i - NX4;
        v = (off < NWS4) ? Ws[off] : Wh[off - NWS4];
        dh = (uint2*)g_whi; dl = (uint2*)g_wlo;
    }
    uint32_t h01, l01, h23, l23;
    split2(v.x, v.y, h01, l01);
    split2(v.z, v.w, h23, l23);
    dh[off] = make_uint2(h01, h23);
    dl[off] = make_uint2(l01, l23);
}

// ============================================================================
// Gates (R5-proven form): one warp per batch row; final weights (both
// softmaxes + sim mask) so combine has zero transcendentals.
// ============================================================================
__global__ __launch_bounds__(256)
void gates_kernel(const float* __restrict__ x,
                  const float* __restrict__ Wg,  const float* __restrict__ bg,
                  const float* __restrict__ Wgs, const float* __restrict__ bgs,
                  const int* __restrict__ sim)
{
    const int gwarp = (blockIdx.x * blockDim.x + threadIdx.x) >> 5;
    const int lane  = threadIdx.x & 31;
    if (gwarp >= BATCH) return;
    const int b = gwarp;

#pragma unroll
    for (int n = 0; n < 4; ++n) {
        const float* xr = x + ((size_t)n * BATCH + b) * DIN;
        float xv[16];
#pragma unroll
        for (int i = 0; i < 16; ++i) xv[i] = xr[lane + 32 * i];
        float zz[6];
#pragma unroll
        for (int e = 0; e < 6; ++e) {
            float acc = 0.f;
#pragma unroll
            for (int i = 0; i < 16; ++i)
                acc = fmaf(xv[i], Wg[(size_t)n * DIN * 6 + (size_t)(lane + 32 * i) * 6 + e], acc);
#pragma unroll
            for (int o = 16; o; o >>= 1) acc += __shfl_xor_sync(0xffffffffu, acc, o);
            zz[e] = acc + bg[n * 6 + e];
        }
        float m1 = zz[0];
#pragma unroll
        for (int e = 1; e < 6; ++e) m1 = fmaxf(m1, zz[e]);
        float s1 = 0.f;
#pragma unroll
        for (int e = 0; e < 6; ++e) { zz[e] = __expf(zz[e] - m1); s1 += zz[e]; }
        const float inv1 = 1.f / s1;
#pragma unroll
        for (int e = 0; e < 6; ++e) zz[e] *= inv1;

        const int s0 = sim[n * 2], s1i = sim[n * 2 + 1];
        bool valid[6];
        valid[0] = true; valid[1] = true;
#pragma unroll
        for (int e = 0; e < 4; ++e) valid[2 + e] = (s0 == e) || (s1i == e);
        float m2 = -1e30f;
#pragma unroll
        for (int e = 0; e < 6; ++e) if (valid[e]) m2 = fmaxf(m2, zz[e]);
        float w[6]; float s2 = 0.f;
#pragma unroll
        for (int e = 0; e < 6; ++e) { w[e] = valid[e] ? __expf(zz[e] - m2) : 0.f; s2 += w[e]; }
        const float inv2 = 1.f / s2;
        if (lane == 0) {
#pragma unroll
            for (int e = 0; e < 6; ++e)
                g_gw[((size_t)n * BATCH + b) * 6 + e] = w[e] * inv2;
        }
    }
    {
        const float* xr = x + ((size_t)4 * BATCH + b) * DIN;
        float xv[16];
#pragma unroll
        for (int i = 0; i < 16; ++i) xv[i] = xr[lane + 32 * i];
        float gs[12];
#pragma unroll
        for (int e = 0; e < 12; ++e) {
            float acc = 0.f;
#pragma unroll
            for (int i = 0; i < 16; ++i)
                acc = fmaf(xv[i], Wgs[(size_t)(lane + 32 * i) * 12 + e], acc);
#pragma unroll
            for (int o = 16; o; o >>= 1) acc += __shfl_xor_sync(0xffffffffu, acc, o);
            gs[e] = acc + bgs[e];
        }
        float m = gs[0];
#pragma unroll
        for (int e = 1; e < 12; ++e) m = fmaxf(m, gs[e]);
        float s = 0.f;
#pragma unroll
        for (int e = 0; e < 12; ++e) { gs[e] = __expf(gs[e] - m); s += gs[e]; }
        const float inv = 1.f / s;
        if (lane == 0) {
#pragma unroll
            for (int e = 0; e < 12; ++e)
                g_gsw[(size_t)b * 12 + e] = gs[e] * inv;
        }
    }
}

// ============================================================================
// Persistent tensor-core GEMM (R6-proven): mma.sync bf16, 3-product split,
// continuous 3-stage cp.async ring across tile boundaries.
// ============================================================================
#define OFF_AHI 0
#define OFF_ALO 10240
#define OFF_BHI 20480
#define OFF_BLO 28672
#define STG     36864
#define GEMM_SMEM (3 * STG)   // 110592

__device__ __forceinline__ void issue_stage(uint32_t sm32, int buf, int tile, int kt, int tid)
{
    const int nt   = tile & 1;
    const int z    = (tile >> 1) % 12;
    const int mblk = tile / 24;
    const int m0 = mblk * 128, n0 = nt * 128, c0 = kt * 32;
    const int zsel = (z < 8) ? (z >> 1) : 4;
    const __nv_bfloat16* xhi = g_xhi + (size_t)zsel * BATCH * DIN;
    const __nv_bfloat16* xlo = g_xlo + (size_t)zsel * BATCH * DIN;
    const __nv_bfloat16* whi = g_whi + (size_t)z * DIN * HDIM;
    const __nv_bfloat16* wlo = g_wlo + (size_t)z * DIN * HDIM;

    const uint32_t sa = sm32 + buf * STG;
    // A: 128 rows x 32k hi/lo, padded rows (80B)
#pragma unroll
    for (int i = 0; i < 2; ++i) {
        const int idx = tid + i * 256;
        const int m = idx >> 2, u = idx & 3;
        const size_t go = (size_t)(m0 + m) * DIN + c0 + u * 8;
        const uint32_t d = sa + OFF_AHI + m * 80 + u * 16;
        cpasync16(d, xhi + go);
        cpasync16(d + (OFF_ALO - OFF_AHI), xlo + go);
    }
    // B: 32 k-rows x 128n hi/lo, XOR-swizzled 16B units
#pragma unroll
    for (int i = 0; i < 2; ++i) {
        const int idx = tid + i * 256;
        const int k = idx >> 4, u = idx & 15;
        const size_t go = (size_t)(c0 + k) * HDIM + n0 + u * 8;
        const uint32_t phys = (u & 8) | ((u & 7) ^ (k & 7));
        const uint32_t d = sa + OFF_BHI + k * 256 + phys * 16;
        cpasync16(d, whi + go);
        cpasync16(d + (OFF_BLO - OFF_BHI), wlo + go);
    }
}

__global__ void __launch_bounds__(256, 2)
gemm_tc(const float* __restrict__ bspec, const float* __restrict__ bsh)
{
    extern __shared__ char smem[];
    const uint32_t sm32 = smem_u32(smem);
    const int tid  = threadIdx.x;
    const int wid  = tid >> 5;
    const int lane = tid & 31;
    const int wm0  = (wid & 3) * 32;
    const int wn0  = (wid >> 2) * 64;

    const int cnt   = (NTILES - blockIdx.x + GRIDP - 1) / GRIDP;
    const int total = cnt * 16;

    float acc[2][8][4];
#pragma unroll
    for (int f = 0; f < 2; ++f)
#pragma unroll
        for (int j = 0; j < 8; ++j)
#pragma unroll
            for (int q = 0; q < 4; ++q) acc[f][j][q] = 0.f;

    // prologue: 2 stages in flight
    issue_stage(sm32, 0, blockIdx.x, 0, tid); CP_COMMIT();
    issue_stage(sm32, 1, blockIdx.x, 1, tid); CP_COMMIT();

    for (int ls = 0; ls < total; ++ls) {
        CP_WAIT1();
        __syncthreads();

        const int ls2 = ls + 2;
        if (ls2 < total)
            issue_stage(sm32, ls2 % 3, blockIdx.x + (ls2 >> 4) * GRIDP, ls2 & 15, tid);
        CP_COMMIT();   // empty group at tail keeps wait accounting consistent

        const uint32_t sa = sm32 + (ls % 3) * STG;
#pragma unroll
        for (int ksb = 0; ksb < 2; ++ksb) {
            const int kb = ksb * 16;
            uint32_t ah[2][4], al[2][4];
#pragma unroll
            for (int f = 0; f < 2; ++f) {
                const uint32_t aaddr = sa + OFF_AHI
                    + (wm0 + f * 16 + (lane & 15)) * 80
                    + (kb + ((lane >> 4) << 3)) * 2;
                ldsm4(ah[f][0], ah[f][1], ah[f][2], ah[f][3], aaddr);
                ldsm4(al[f][0], al[f][1], al[f][2], al[f][3], aaddr + (OFF_ALO - OFF_AHI));
            }
            const int g = lane >> 3, r = lane & 7;
            const int krow = kb + (g & 1) * 8 + r;
#pragma unroll
            for (int c = 0; c < 4; ++c) {
                const int noff = wn0 + c * 16 + (g >> 1) * 8;
                const uint32_t u = (uint32_t)(noff >> 3);
                const uint32_t phys = (u & 8) | ((u & 7) ^ (uint32_t)(krow & 7));
                const uint32_t baddr = sa + OFF_BHI + krow * 256 + phys * 16;
                uint32_t bh[4], bl[4];
                ldsm4t(bh[0], bh[1], bh[2], bh[3], baddr);
                ldsm4t(bl[0], bl[1], bl[2], bl[3], baddr + (OFF_BLO - OFF_BHI));
#pragma unroll
                for (int f = 0; f < 2; ++f) {
#pragma unroll
                    for (int jj = 0; jj < 2; ++jj) {
                        float* d = acc[f][2 * c + jj];
                        mma16816(d, ah[f], bh[2 * jj], bh[2 * jj + 1]);
                        mma16816(d, ah[f], bl[2 * jj], bl[2 * jj + 1]);
                        mma16816(d, al[f], bh[2 * jj], bh[2 * jj + 1]);
                    }
                }
            }
        }

        if ((ls & 15) == 15) {
            // tile epilogue: reg -> global only (no smem), overlaps next loads
            const int tile = blockIdx.x + (ls >> 4) * GRIDP;
            const int nt   = tile & 1;
            const int z    = (tile >> 1) % 12;
            const int mblk = tile / 24;
            const int m0 = mblk * 128, n0 = nt * 128;
            const float* bias = (z < 8) ? (bspec + z * HDIM) : (bsh + (z - 8) * HDIM);
            float* outp = (z < 8) ? (g_spec + (size_t)z * BATCH * HDIM)
                                  : (g_shared + (size_t)(z - 8) * BATCH * HDIM);
#pragma unroll
            for (int f = 0; f < 2; ++f) {
#pragma unroll
                for (int j = 0; j < 8; ++j) {
                    const int row = m0 + wm0 + f * 16 + (lane >> 2);
                    const int col = n0 + wn0 + j * 8 + (lane & 3) * 2;
                    const float b0 = __ldg(&bias[col]);
                    const float b1 = __ldg(&bias[col + 1]);
                    float2 v0, v1;
                    v0.x = fmaxf(acc[f][j][0] + b0, 0.f);
                    v0.y = fmaxf(acc[f][j][1] + b1, 0.f);
                    v1.x = fmaxf(acc[f][j][2] + b0, 0.f);
                    v1.y = fmaxf(acc[f][j][3] + b1, 0.f);
                    *(float2*)(outp + (size_t)row * HDIM + col)       = v0;
                    *(float2*)(outp + (size_t)(row + 8) * HDIM + col) = v1;
#pragma unroll
                    for (int q = 0; q < 4; ++q) acc[f][j][q] = 0.f;
                }
            }
        }
    }
}

// ============================================================================
// Combine (R6-proven): 4 rows per block, float4 per thread, no transcendentals.
// ============================================================================
__global__ __launch_bounds__(256)
void combine_kernel(float* __restrict__ out)
{
    __shared__ float w[4][36];
    const int b0  = blockIdx.x * 4;
    const int tid = threadIdx.x;
    if (tid < 144) {
        const int row = tid / 36, e = tid % 36;
        float v;
        if (e < 24) v = g_gw[((size_t)(e / 6) * BATCH + b0 + row) * 6 + (e % 6)];
        else        v = g_gsw[(size_t)(b0 + row) * 12 + (e - 24)];
        w[row][e] = v;
    }
    __syncthreads();

    const int r = tid >> 6;
    const int b = b0 + r;
    const int h = (tid & 63) * 4;

    float4 sp[8];
#pragma unroll
    for (int j = 0; j < 8; ++j)
        sp[j] = *(const float4*)&g_spec[((size_t)j * BATCH + b) * HDIM + h];
    float4 sh[4];
#pragma unroll
    for (int e = 0; e < 4; ++e)
        sh[e] = *(const float4*)&g_shared[((size_t)e * BATCH + b) * HDIM + h];

    // shared-gate output
    {
        float4 o = make_float4(0.f, 0.f, 0.f, 0.f);
#pragma unroll
        for (int j = 0; j < 8; ++j) {
            const float ww = w[r][24 + j];
            o.x = fmaf(ww, sp[j].x, o.x); o.y = fmaf(ww, sp[j].y, o.y);
            o.z = fmaf(ww, sp[j].z, o.z); o.w = fmaf(ww, sp[j].w, o.w);
        }
#pragma unroll
        for (int e = 0; e < 4; ++e) {
            const float ww = w[r][32 + e];
            o.x = fmaf(ww, sh[e].x, o.x); o.y = fmaf(ww, sh[e].y, o.y);
            o.z = fmaf(ww, sh[e].z, o.z); o.w = fmaf(ww, sh[e].w, o.w);
        }
        *(float4*)&out[((size_t)4 * BATCH + b) * HDIM + h] = o;
    }

    // per-domain outputs
#pragma unroll
    for (int n = 0; n < 4; ++n) {
        float4 o = make_float4(0.f, 0.f, 0.f, 0.f);
        const float w0 = w[r][n * 6 + 0], w1 = w[r][n * 6 + 1];
        o.x = w0 * sp[2 * n].x + w1 * sp[2 * n + 1].x;
        o.y = w0 * sp[2 * n].y + w1 * sp[2 * n + 1].y;
        o.z = w0 * sp[2 * n].z + w1 * sp[2 * n + 1].z;
        o.w = w0 * sp[2 * n].w + w1 * sp[2 * n + 1].w;
#pragma unroll
        for (int e = 0; e < 4; ++e) {
            const float ww = w[r][n * 6 + 2 + e];
            o.x = fmaf(ww, sh[e].x, o.x); o.y = fmaf(ww, sh[e].y, o.y);
            o.z = fmaf(ww, sh[e].z, o.z); o.w = fmaf(ww, sh[e].w, o.w);
        }
        *(float4*)&out[((size_t)n * BATCH + b) * HDIM + h] = o;
    }
}

// ============================================================================
extern "C" void kernel_launch(void* const* d_in, const int* in_sizes, int n_in,
                              void* d_out, int out_size)
{
    const float* x     = (const float*)d_in[0];
    const int*   sim   = (const int*)d_in[1];
    const float* Wspec = (const float*)d_in[2];
    const float* bspec = (const float*)d_in[3];
    const float* Wsh   = (const float*)d_in[4];
    const float* bsh   = (const float*)d_in[5];
    const float* Wg    = (const float*)d_in[6];
    const float* bg    = (const float*)d_in[7];
    const float* Wgs   = (const float*)d_in[8];
    const float* bgs   = (const float*)d_in[9];
    float* out = (float*)d_out;

    split_kernel<<<NSPLIT_BLOCKS, 256>>>((const float4*)x, (const float4*)Wspec,
                                         (const float4*)Wsh);

    gates_kernel<<<BATCH / 8, 256>>>(x, Wg, bg, Wgs, bgs, sim);

    cudaFuncSetAttribute(gemm_tc, cudaFuncAttributeMaxDynamicSharedMemorySize, GEMM_SMEM);
    gemm_tc<<<GRIDP, 256, GEMM_SMEM>>>(bspec, bsh);

    combine_kernel<<<BATCH / 4, 256>>>(out);
}

// round 9
// speedup vs baseline: 1.5144x; 1.0459x over previous
#include <cuda_runtime.h>
#include <cuda_bf16.h>
#include <math.h>
#include <stdint.h>

#define BATCH 16384
#define DIN   512
#define HDIM  256

// -------- scratch (static device allocations; no cudaMalloc allowed) --------
__device__ float g_spec[8 * BATCH * HDIM];            // [z][b][h]
__device__ float g_shared[4 * BATCH * HDIM];          // [e][b][h]
__device__ float g_gw[4 * BATCH * 6];                 // FINAL domain gate weights
__device__ float g_gsw[BATCH * 12];                   // FINAL shared gate weights
__device__ __nv_bfloat16 g_xhi[5 * BATCH * DIN];
__device__ __nv_bfloat16 g_xlo[5 * BATCH * DIN];
__device__ __nv_bfloat16 g_whi[12 * DIN * HDIM];      // [z][k][n]
__device__ __nv_bfloat16 g_wlo[12 * DIN * HDIM];

// ============================================================================
// helpers
// ============================================================================
__device__ __forceinline__ uint32_t smem_u32(const void* p) {
    uint32_t a;
    asm("{ .reg .u64 t; cvta.to.shared.u64 t, %1; cvt.u32.u64 %0, t; }" : "=r"(a) : "l"(p));
    return a;
}
__device__ __forceinline__ void cpasync16(uint32_t dst, const void* src) {
    asm volatile("cp.async.cg.shared.global [%0], [%1], 16;" :: "r"(dst), "l"(src) : "memory");
}
#define CP_COMMIT() asm volatile("cp.async.commit_group;" ::: "memory")
#define CP_WAIT1()  asm volatile("cp.async.wait_group 1;" ::: "memory")

__device__ __forceinline__ void ldsm4(uint32_t& r0, uint32_t& r1, uint32_t& r2, uint32_t& r3, uint32_t addr) {
    asm volatile("ldmatrix.sync.aligned.m8n8.x4.shared.b16 {%0,%1,%2,%3}, [%4];"
                 : "=r"(r0), "=r"(r1), "=r"(r2), "=r"(r3) : "r"(addr));
}
__device__ __forceinline__ void ldsm4t(uint32_t& r0, uint32_t& r1, uint32_t& r2, uint32_t& r3, uint32_t addr) {
    asm volatile("ldmatrix.sync.aligned.m8n8.x4.trans.shared.b16 {%0,%1,%2,%3}, [%4];"
                 : "=r"(r0), "=r"(r1), "=r"(r2), "=r"(r3) : "r"(addr));
}
__device__ __forceinline__ void mma16816(float* d, const uint32_t* a, uint32_t b0, uint32_t b1) {
    asm volatile(
        "mma.sync.aligned.m16n8k16.row.col.f32.bf16.bf16.f32 "
        "{%0,%1,%2,%3}, {%4,%5,%6,%7}, {%8,%9}, {%0,%1,%2,%3};"
        : "+f"(d[0]), "+f"(d[1]), "+f"(d[2]), "+f"(d[3])
        : "r"(a[0]), "r"(a[1]), "r"(a[2]), "r"(a[3]), "r"(b0), "r"(b1));
}

__device__ __forceinline__ void split2(float a0, float a1, uint32_t& hi, uint32_t& lo) {
    __nv_bfloat16 h0 = __float2bfloat16(a0);
    __nv_bfloat16 h1 = __float2bfloat16(a1);
    __nv_bfloat16 l0 = __float2bfloat16(a0 - __bfloat162float(h0));
    __nv_bfloat16 l1 = __float2bfloat16(a1 - __bfloat162float(h1));
    hi = ((uint32_t)__bfloat16_as_ushort(h1) << 16) | __bfloat16_as_ushort(h0);
    lo = ((uint32_t)__bfloat16_as_ushort(l1) << 16) | __bfloat16_as_ushort(l0);
}

// ============================================================================
// Branchless split kernels: f32 -> (bf16 hi, bf16 lo), MLP=4.
// ============================================================================
#define NX4  (5 * BATCH * DIN / 4)          // 10485760 float4
#define NWS4 (8 * DIN * HDIM / 4)           // 262144
#define NWH4 (4 * DIN * HDIM / 4)           // 131072
#define XBLOCKS (NX4 / 1024)                // 10240
#define WSBLK   (NWS4 / 1024)               // 256
#define WHBLK   (NWH4 / 1024)               // 128

__global__ __launch_bounds__(256)
void split_x_kernel(const float4* __restrict__ x)
{
    const size_t base = (size_t)blockIdx.x * 1024 + threadIdx.x;
    float4 v0 = x[base];
    float4 v1 = x[base + 256];
    float4 v2 = x[base + 512];
    float4 v3 = x[base + 768];
    uint2* dh = (uint2*)g_xhi;
    uint2* dl = (uint2*)g_xlo;
    uint32_t ha, la, hb, lb;
    split2(v0.x, v0.y, ha, la); split2(v0.z, v0.w, hb, lb);
    dh[base]       = make_uint2(ha, hb); dl[base]       = make_uint2(la, lb);
    split2(v1.x, v1.y, ha, la); split2(v1.z, v1.w, hb, lb);
    dh[base + 256] = make_uint2(ha, hb); dl[base + 256] = make_uint2(la, lb);
    split2(v2.x, v2.y, ha, la); split2(v2.z, v2.w, hb, lb);
    dh[base + 512] = make_uint2(ha, hb); dl[base + 512] = make_uint2(la, lb);
    split2(v3.x, v3.y, ha, la); split2(v3.z, v3.w, hb, lb);
    dh[base + 768] = make_uint2(ha, hb); dl[base + 768] = make_uint2(la, lb);
}

__global__ __launch_bounds__(256)
void split_w_kernel(const float4* __restrict__ Ws, const float4* __restrict__ Wh)
{
    // block-uniform region select: blocks [0,WSBLK) -> Ws, [WSBLK, WSBLK+WHBLK) -> Wh
    const float4* src;
    size_t dst0;
    if (blockIdx.x < WSBLK) {
        src  = Ws + (size_t)blockIdx.x * 1024;
        dst0 = (size_t)blockIdx.x * 1024;
    } else {
        src  = Wh + (size_t)(blockIdx.x - WSBLK) * 1024;
        dst0 = (size_t)NWS4 + (size_t)(blockIdx.x - WSBLK) * 1024;
    }
    const int t = threadIdx.x;
    float4 v0 = src[t];
    float4 v1 = src[t + 256];
    float4 v2 = src[t + 512];
    float4 v3 = src[t + 768];
    uint2* dh = (uint2*)g_whi;
    uint2* dl = (uint2*)g_wlo;
    uint32_t ha, la, hb, lb;
    split2(v0.x, v0.y, ha, la); split2(v0.z, v0.w, hb, lb);
    dh[dst0 + t]       = make_uint2(ha, hb); dl[dst0 + t]       = make_uint2(la, lb);
    split2(v1.x, v1.y, ha, la); split2(v1.z, v1.w, hb, lb);
    dh[dst0 + t + 256] = make_uint2(ha, hb); dl[dst0 + t + 256] = make_uint2(la, lb);
    split2(v2.x, v2.y, ha, la); split2(v2.z, v2.w, hb, lb);
    dh[dst0 + t + 512] = make_uint2(ha, hb); dl[dst0 + t + 512] = make_uint2(la, lb);
    split2(v3.x, v3.y, ha, la); split2(v3.z, v3.w, hb, lb);
    dh[dst0 + t + 768] = make_uint2(ha, hb); dl[dst0 + t + 768] = make_uint2(la, lb);
}

// ============================================================================
// Gates (R5-proven): one warp per batch row; final weights (both softmaxes
// + sim mask) so combine has zero transcendentals.
// ============================================================================
__global__ __launch_bounds__(256)
void gates_kernel(const float* __restrict__ x,
                  const float* __restrict__ Wg,  const float* __restrict__ bg,
                  const float* __restrict__ Wgs, const float* __restrict__ bgs,
                  const int* __restrict__ sim)
{
    const int gwarp = (blockIdx.x * blockDim.x + threadIdx.x) >> 5;
    const int lane  = threadIdx.x & 31;
    if (gwarp >= BATCH) return;
    const int b = gwarp;

#pragma unroll
    for (int n = 0; n < 4; ++n) {
        const float* xr = x + ((size_t)n * BATCH + b) * DIN;
        float xv[16];
#pragma unroll
        for (int i = 0; i < 16; ++i) xv[i] = xr[lane + 32 * i];
        float zz[6];
#pragma unroll
        for (int e = 0; e < 6; ++e) {
            float acc = 0.f;
#pragma unroll
            for (int i = 0; i < 16; ++i)
                acc = fmaf(xv[i], Wg[(size_t)n * DIN * 6 + (size_t)(lane + 32 * i) * 6 + e], acc);
#pragma unroll
            for (int o = 16; o; o >>= 1) acc += __shfl_xor_sync(0xffffffffu, acc, o);
            zz[e] = acc + bg[n * 6 + e];
        }
        float m1 = zz[0];
#pragma unroll
        for (int e = 1; e < 6; ++e) m1 = fmaxf(m1, zz[e]);
        float s1 = 0.f;
#pragma unroll
        for (int e = 0; e < 6; ++e) { zz[e] = __expf(zz[e] - m1); s1 += zz[e]; }
        const float inv1 = 1.f / s1;
#pragma unroll
        for (int e = 0; e < 6; ++e) zz[e] *= inv1;

        const int s0 = sim[n * 2], s1i = sim[n * 2 + 1];
        bool valid[6];
        valid[0] = true; valid[1] = true;
#pragma unroll
        for (int e = 0; e < 4; ++e) valid[2 + e] = (s0 == e) || (s1i == e);
        float m2 = -1e30f;
#pragma unroll
        for (int e = 0; e < 6; ++e) if (valid[e]) m2 = fmaxf(m2, zz[e]);
        float w[6]; float s2 = 0.f;
#pragma unroll
        for (int e = 0; e < 6; ++e) { w[e] = valid[e] ? __expf(zz[e] - m2) : 0.f; s2 += w[e]; }
        const float inv2 = 1.f / s2;
        if (lane == 0) {
#pragma unroll
            for (int e = 0; e < 6; ++e)
                g_gw[((size_t)n * BATCH + b) * 6 + e] = w[e] * inv2;
        }
    }
    {
        const float* xr = x + ((size_t)4 * BATCH + b) * DIN;
        float xv[16];
#pragma unroll
        for (int i = 0; i < 16; ++i) xv[i] = xr[lane + 32 * i];
        float gs[12];
#pragma unroll
        for (int e = 0; e < 12; ++e) {
            float acc = 0.f;
#pragma unroll
            for (int i = 0; i < 16; ++i)
                acc = fmaf(xv[i], Wgs[(size_t)(lane + 32 * i) * 12 + e], acc);
#pragma unroll
            for (int o = 16; o; o >>= 1) acc += __shfl_xor_sync(0xffffffffu, acc, o);
            gs[e] = acc + bgs[e];
        }
        float m = gs[0];
#pragma unroll
        for (int e = 1; e < 12; ++e) m = fmaxf(m, gs[e]);
        float s = 0.f;
#pragma unroll
        for (int e = 0; e < 12; ++e) { gs[e] = __expf(gs[e] - m); s += gs[e]; }
        const float inv = 1.f / s;
        if (lane == 0) {
#pragma unroll
            for (int e = 0; e < 12; ++e)
                g_gsw[(size_t)b * 12 + e] = gs[e] * inv;
        }
    }
}

// ============================================================================
// Tensor-core GEMM (R5-proven grid version): mma.sync bf16, 3-product split,
// CTA tile 128x128, BK=32, 3-stage cp.async pipeline, 2 CTAs/SM.
// ============================================================================
#define OFF_AHI 0
#define OFF_ALO 10240
#define OFF_BHI 20480
#define OFF_BLO 28672
#define STG     36864
#define GEMM_SMEM (3 * STG)   // 110592

__device__ __forceinline__ void issue_chunk(
    uint32_t sm32, int stage, int c0,
    const __nv_bfloat16* __restrict__ xhi, const __nv_bfloat16* __restrict__ xlo,
    const __nv_bfloat16* __restrict__ whi, const __nv_bfloat16* __restrict__ wlo,
    int m0, int n0, int tid)
{
    const uint32_t sa = sm32 + stage * STG;
#pragma unroll
    for (int i = 0; i < 2; ++i) {
        const int idx = tid + i * 256;
        const int m = idx >> 2, u = idx & 3;
        const size_t go = (size_t)(m0 + m) * DIN + c0 + u * 8;
        const uint32_t d = sa + OFF_AHI + m * 80 + u * 16;
        cpasync16(d, xhi + go);
        cpasync16(d + (OFF_ALO - OFF_AHI), xlo + go);
    }
#pragma unroll
    for (int i = 0; i < 2; ++i) {
        const int idx = tid + i * 256;
        const int k = idx >> 4, u = idx & 15;
        const size_t go = (size_t)(c0 + k) * HDIM + n0 + u * 8;
        const uint32_t phys = (u & 8) | ((u & 7) ^ (k & 7));
        const uint32_t d = sa + OFF_BHI + k * 256 + phys * 16;
        cpasync16(d, whi + go);
        cpasync16(d + (OFF_BLO - OFF_BHI), wlo + go);
    }
}

__global__ void __launch_bounds__(256, 2)
gemm_tc(const float* __restrict__ bspec, const float* __restrict__ bsh)
{
    extern __shared__ char smem[];
    const uint32_t sm32 = smem_u32(smem);
    const int tid  = threadIdx.x;
    const int wid  = tid >> 5;
    const int lane = tid & 31;
    const int wm0  = (wid & 3) * 32;
    const int wn0  = (wid >> 2) * 64;

    const int n0 = blockIdx.x * 128;
    const int m0 = blockIdx.y * 128;
    const int z  = blockIdx.z;

    const int zsel = (z < 8) ? (z >> 1) : 4;
    const __nv_bfloat16* xhi = g_xhi + (size_t)zsel * BATCH * DIN;
    const __nv_bfloat16* xlo = g_xlo + (size_t)zsel * BATCH * DIN;
    const __nv_bfloat16* whi = g_whi + (size_t)z * DIN * HDIM;
    const __nv_bfloat16* wlo = g_wlo + (size_t)z * DIN * HDIM;
    const float* bias = (z < 8) ? (bspec + z * HDIM) : (bsh + (z - 8) * HDIM);
    float* outp = (z < 8) ? (g_spec + (size_t)z * BATCH * HDIM)
                          : (g_shared + (size_t)(z - 8) * BATCH * HDIM);

    float acc[2][8][4];
#pragma unroll
    for (int f = 0; f < 2; ++f)
#pragma unroll
        for (int j = 0; j < 8; ++j)
#pragma unroll
            for (int q = 0; q < 4; ++q) acc[f][j][q] = 0.f;

    // prologue: 2 stages in flight
#pragma unroll
    for (int p = 0; p < 2; ++p) {
        issue_chunk(sm32, p, p * 32, xhi, xlo, whi, wlo, m0, n0, tid);
        CP_COMMIT();
    }

    for (int kt = 0; kt < 16; ++kt) {
        CP_WAIT1();
        __syncthreads();

        if (kt + 2 < 16)
            issue_chunk(sm32, (kt + 2) % 3, (kt + 2) * 32, xhi, xlo, whi, wlo, m0, n0, tid);
        CP_COMMIT();

        const uint32_t sa = sm32 + (kt % 3) * STG;
#pragma unroll
        for (int ksb = 0; ksb < 2; ++ksb) {
            const int kb = ksb * 16;
            uint32_t ah[2][4], al[2][4];
#pragma unroll
            for (int f = 0; f < 2; ++f) {
                const uint32_t aaddr = sa + OFF_AHI
                    + (wm0 + f * 16 + (lane & 15)) * 80
                    + (kb + ((lane >> 4) << 3)) * 2;
                ldsm4(ah[f][0], ah[f][1], ah[f][2], ah[f][3], aaddr);
                ldsm4(al[f][0], al[f][1], al[f][2], al[f][3], aaddr + (OFF_ALO - OFF_AHI));
            }
            const int g = lane >> 3, r = lane & 7;
            const int krow = kb + (g & 1) * 8 + r;
#pragma unroll
            for (int c = 0; c < 4; ++c) {
                const int noff = wn0 + c * 16 + (g >> 1) * 8;
                const uint32_t u = (uint32_t)(noff >> 3);
                const uint32_t phys = (u & 8) | ((u & 7) ^ (uint32_t)(krow & 7));
                const uint32_t baddr = sa + OFF_BHI + krow * 256 + phys * 16;
                uint32_t bh[4], bl[4];
                ldsm4t(bh[0], bh[1], bh[2], bh[3], baddr);
                ldsm4t(bl[0], bl[1], bl[2], bl[3], baddr + (OFF_BLO - OFF_BHI));
#pragma unroll
                for (int f = 0; f < 2; ++f) {
#pragma unroll
                    for (int jj = 0; jj < 2; ++jj) {
                        float* d = acc[f][2 * c + jj];
                        mma16816(d, ah[f], bh[2 * jj], bh[2 * jj + 1]);
                        mma16816(d, ah[f], bl[2 * jj], bl[2 * jj + 1]);
                        mma16816(d, al[f], bh[2 * jj], bh[2 * jj + 1]);
                    }
                }
            }
        }
    }

    // epilogue: bias + relu, direct global stores
#pragma unroll
    for (int f = 0; f < 2; ++f) {
#pragma unroll
        for (int j = 0; j < 8; ++j) {
            const int row = m0 + wm0 + f * 16 + (lane >> 2);
            const int col = n0 + wn0 + j * 8 + (lane & 3) * 2;
            const float b0 = __ldg(&bias[col]);
            const float b1 = __ldg(&bias[col + 1]);
            float2 v0, v1;
            v0.x = fmaxf(acc[f][j][0] + b0, 0.f);
            v0.y = fmaxf(acc[f][j][1] + b1, 0.f);
            v1.x = fmaxf(acc[f][j][2] + b0, 0.f);
            v1.y = fmaxf(acc[f][j][3] + b1, 0.f);
            *(float2*)(outp + (size_t)row * HDIM + col)       = v0;
            *(float2*)(outp + (size_t)(row + 8) * HDIM + col) = v1;
        }
    }
}

// ============================================================================
// Combine (R8-proven): 4 rows per block, float4 per thread, no transcendentals.
// ============================================================================
__global__ __launch_bounds__(256)
void combine_kernel(float* __restrict__ out)
{
    __shared__ float w[4][36];
    const int b0  = blockIdx.x * 4;
    const int tid = threadIdx.x;
    if (tid < 144) {
        const int row = tid / 36, e = tid % 36;
        float v;
        if (e < 24) v = g_gw[((size_t)(e / 6) * BATCH + b0 + row) * 6 + (e % 6)];
        else        v = g_gsw[(size_t)(b0 + row) * 12 + (e - 24)];
        w[row][e] = v;
    }
    __syncthreads();

    const int r = tid >> 6;
    const int b = b0 + r;
    const int h = (tid & 63) * 4;

    float4 sp[8];
#pragma unroll
    for (int j = 0; j < 8; ++j)
        sp[j] = *(const float4*)&g_spec[((size_t)j * BATCH + b) * HDIM + h];
    float4 sh[4];
#pragma unroll
    for (int e = 0; e < 4; ++e)
        sh[e] = *(const float4*)&g_shared[((size_t)e * BATCH + b) * HDIM + h];

    {
        float4 o = make_float4(0.f, 0.f, 0.f, 0.f);
#pragma unroll
        for (int j = 0; j < 8; ++j) {
            const float ww = w[r][24 + j];
            o.x = fmaf(ww, sp[j].x, o.x); o.y = fmaf(ww, sp[j].y, o.y);
            o.z = fmaf(ww, sp[j].z, o.z); o.w = fmaf(ww, sp[j].w, o.w);
        }
#pragma unroll
        for (int e = 0; e < 4; ++e) {
            const float ww = w[r][32 + e];
            o.x = fmaf(ww, sh[e].x, o.x); o.y = fmaf(ww, sh[e].y, o.y);
            o.z = fmaf(ww, sh[e].z, o.z); o.w = fmaf(ww, sh[e].w, o.w);
        }
        *(float4*)&out[((size_t)4 * BATCH + b) * HDIM + h] = o;
    }

#pragma unroll
    for (int n = 0; n < 4; ++n) {
        float4 o = make_float4(0.f, 0.f, 0.f, 0.f);
        const float w0 = w[r][n * 6 + 0], w1 = w[r][n * 6 + 1];
        o.x = w0 * sp[2 * n].x + w1 * sp[2 * n + 1].x;
        o.y = w0 * sp[2 * n].y + w1 * sp[2 * n + 1].y;
        o.z = w0 * sp[2 * n].z + w1 * sp[2 * n + 1].z;
        o.w = w0 * sp[2 * n].w + w1 * sp[2 * n + 1].w;
#pragma unroll
        for (int e = 0; e < 4; ++e) {
            const float ww = w[r][n * 6 + 2 + e];
            o.x = fmaf(ww, sh[e].x, o.x); o.y = fmaf(ww, sh[e].y, o.y);
            o.z = fmaf(ww, sh[e].z, o.z); o.w = fmaf(ww, sh[e].w, o.w);
        }
        *(float4*)&out[((size_t)n * BATCH + b) * HDIM + h] = o;
    }
}

// ============================================================================
extern "C" void kernel_launch(void* const* d_in, const int* in_sizes, int n_in,
                              void* d_out, int out_size)
{
    const float* x     = (const float*)d_in[0];
    const int*   sim   = (const int*)d_in[1];
    const float* Wspec = (const float*)d_in[2];
    const float* bspec = (const float*)d_in[3];
    const float* Wsh   = (const float*)d_in[4];
    const float* bsh   = (const float*)d_in[5];
    const float* Wg    = (const float*)d_in[6];
    const float* bg    = (const float*)d_in[7];
    const float* Wgs   = (const float*)d_in[8];
    const float* bgs   = (const float*)d_in[9];
    float* out = (float*)d_out;

    split_x_kernel<<<XBLOCKS, 256>>>((const float4*)x);
    split_w_kernel<<<WSBLK + WHBLK, 256>>>((const float4*)Wspec, (const float4*)Wsh);

    gates_kernel<<<BATCH / 8, 256>>>(x, Wg, bg, Wgs, bgs, sim);

    cudaFuncSetAttribute(gemm_tc, cudaFuncAttributeMaxDynamicSharedMemorySize, GEMM_SMEM);
    dim3 gemm_grid(2, 128, 12);
    gemm_tc<<<gemm_grid, 256, GEMM_SMEM>>>(bspec, bsh);

    combine_kernel<<<BATCH / 4, 256>>>(out);
}

// round 10
// speedup vs baseline: 1.5384x; 1.0158x over previous
#include <cuda_runtime.h>
#include <cuda_bf16.h>
#include <math.h>
#include <stdint.h>

#define BATCH 16384
#define DIN   512
#define HDIM  256

// -------- scratch (static device allocations; no cudaMalloc allowed) --------
__device__ float g_spec[8 * BATCH * HDIM];            // [z][b][h]
__device__ float g_shared[4 * BATCH * HDIM];          // [e][b][h]
__device__ float g_gw[4 * BATCH * 6];                 // FINAL domain gate weights
__device__ float g_gsw[BATCH * 12];                   // FINAL shared gate weights
__device__ __nv_bfloat16 g_whi[12 * DIN * HDIM];      // [z][k][n]
__device__ __nv_bfloat16 g_wlo[12 * DIN * HDIM];

// ============================================================================
// helpers
// ============================================================================
__device__ __forceinline__ uint32_t smem_u32(const void* p) {
    uint32_t a;
    asm("{ .reg .u64 t; cvta.to.shared.u64 t, %1; cvt.u32.u64 %0, t; }" : "=r"(a) : "l"(p));
    return a;
}
__device__ __forceinline__ void cpasync16(uint32_t dst, const void* src) {
    asm volatile("cp.async.cg.shared.global [%0], [%1], 16;" :: "r"(dst), "l"(src) : "memory");
}
#define CP_COMMIT() asm volatile("cp.async.commit_group;" ::: "memory")
#define CP_WAIT1()  asm volatile("cp.async.wait_group 1;" ::: "memory")

__device__ __forceinline__ void ldsm4t(uint32_t& r0, uint32_t& r1, uint32_t& r2, uint32_t& r3, uint32_t addr) {
    asm volatile("ldmatrix.sync.aligned.m8n8.x4.trans.shared.b16 {%0,%1,%2,%3}, [%4];"
                 : "=r"(r0), "=r"(r1), "=r"(r2), "=r"(r3) : "r"(addr));
}
__device__ __forceinline__ void mma16816(float* d, const uint32_t* a, uint32_t b0, uint32_t b1) {
    asm volatile(
        "mma.sync.aligned.m16n8k16.row.col.f32.bf16.bf16.f32 "
        "{%0,%1,%2,%3}, {%4,%5,%6,%7}, {%8,%9}, {%0,%1,%2,%3};"
        : "+f"(d[0]), "+f"(d[1]), "+f"(d[2]), "+f"(d[3])
        : "r"(a[0]), "r"(a[1]), "r"(a[2]), "r"(a[3]), "r"(b0), "r"(b1));
}

__device__ __forceinline__ void split2(float a0, float a1, uint32_t& hi, uint32_t& lo) {
    __nv_bfloat16 h0 = __float2bfloat16(a0);
    __nv_bfloat16 h1 = __float2bfloat16(a1);
    __nv_bfloat16 l0 = __float2bfloat16(a0 - __bfloat162float(h0));
    __nv_bfloat16 l1 = __float2bfloat16(a1 - __bfloat162float(h1));
    hi = ((uint32_t)__bfloat16_as_ushort(h1) << 16) | __bfloat16_as_ushort(h0);
    lo = ((uint32_t)__bfloat16_as_ushort(l1) << 16) | __bfloat16_as_ushort(l0);
}

// ============================================================================
// Weight split only (x is consumed as f32 directly by the GEMM now).
// ============================================================================
#define NWS4 (8 * DIN * HDIM / 4)           // 262144 float4
#define NWH4 (4 * DIN * HDIM / 4)           // 131072
#define WSBLK   (NWS4 / 1024)               // 256
#define WHBLK   (NWH4 / 1024)               // 128

__global__ __launch_bounds__(256)
void split_w_kernel(const float4* __restrict__ Ws, const float4* __restrict__ Wh)
{
    const float4* src;
    size_t dst0;
    if (blockIdx.x < WSBLK) {
        src  = Ws + (size_t)blockIdx.x * 1024;
        dst0 = (size_t)blockIdx.x * 1024;
    } else {
        src  = Wh + (size_t)(blockIdx.x - WSBLK) * 1024;
        dst0 = (size_t)NWS4 + (size_t)(blockIdx.x - WSBLK) * 1024;
    }
    const int t = threadIdx.x;
    float4 v0 = src[t];
    float4 v1 = src[t + 256];
    float4 v2 = src[t + 512];
    float4 v3 = src[t + 768];
    uint2* dh = (uint2*)g_whi;
    uint2* dl = (uint2*)g_wlo;
    uint32_t ha, la, hb, lb;
    split2(v0.x, v0.y, ha, la); split2(v0.z, v0.w, hb, lb);
    dh[dst0 + t]       = make_uint2(ha, hb); dl[dst0 + t]       = make_uint2(la, lb);
    split2(v1.x, v1.y, ha, la); split2(v1.z, v1.w, hb, lb);
    dh[dst0 + t + 256] = make_uint2(ha, hb); dl[dst0 + t + 256] = make_uint2(la, lb);
    split2(v2.x, v2.y, ha, la); split2(v2.z, v2.w, hb, lb);
    dh[dst0 + t + 512] = make_uint2(ha, hb); dl[dst0 + t + 512] = make_uint2(la, lb);
    split2(v3.x, v3.y, ha, la); split2(v3.z, v3.w, hb, lb);
    dh[dst0 + t + 768] = make_uint2(ha, hb); dl[dst0 + t + 768] = make_uint2(la, lb);
}

// ============================================================================
// Gates: one warp per batch row; final weights (both softmaxes + sim mask).
// ============================================================================
__global__ __launch_bounds__(256)
void gates_kernel(const float* __restrict__ x,
                  const float* __restrict__ Wg,  const float* __restrict__ bg,
                  const float* __restrict__ Wgs, const float* __restrict__ bgs,
                  const int* __restrict__ sim)
{
    const int gwarp = (blockIdx.x * blockDim.x + threadIdx.x) >> 5;
    const int lane  = threadIdx.x & 31;
    if (gwarp >= BATCH) return;
    const int b = gwarp;

#pragma unroll
    for (int n = 0; n < 4; ++n) {
        const float* xr = x + ((size_t)n * BATCH + b) * DIN;
        float xv[16];
#pragma unroll
        for (int i = 0; i < 16; ++i) xv[i] = xr[lane + 32 * i];
        float zz[6];
#pragma unroll
        for (int e = 0; e < 6; ++e) {
            float acc = 0.f;
#pragma unroll
            for (int i = 0; i < 16; ++i)
                acc = fmaf(xv[i], Wg[(size_t)n * DIN * 6 + (size_t)(lane + 32 * i) * 6 + e], acc);
#pragma unroll
            for (int o = 16; o; o >>= 1) acc += __shfl_xor_sync(0xffffffffu, acc, o);
            zz[e] = acc + bg[n * 6 + e];
        }
        float m1 = zz[0];
#pragma unroll
        for (int e = 1; e < 6; ++e) m1 = fmaxf(m1, zz[e]);
        float s1 = 0.f;
#pragma unroll
        for (int e = 0; e < 6; ++e) { zz[e] = __expf(zz[e] - m1); s1 += zz[e]; }
        const float inv1 = 1.f / s1;
#pragma unroll
        for (int e = 0; e < 6; ++e) zz[e] *= inv1;

        const int s0 = sim[n * 2], s1i = sim[n * 2 + 1];
        bool valid[6];
        valid[0] = true; valid[1] = true;
#pragma unroll
        for (int e = 0; e < 4; ++e) valid[2 + e] = (s0 == e) || (s1i == e);
        float m2 = -1e30f;
#pragma unroll
        for (int e = 0; e < 6; ++e) if (valid[e]) m2 = fmaxf(m2, zz[e]);
        float w[6]; float s2 = 0.f;
#pragma unroll
        for (int e = 0; e < 6; ++e) { w[e] = valid[e] ? __expf(zz[e] - m2) : 0.f; s2 += w[e]; }
        const float inv2 = 1.f / s2;
        if (lane == 0) {
#pragma unroll
            for (int e = 0; e < 6; ++e)
                g_gw[((size_t)n * BATCH + b) * 6 + e] = w[e] * inv2;
        }
    }
    {
        const float* xr = x + ((size_t)4 * BATCH + b) * DIN;
        float xv[16];
#pragma unroll
        for (int i = 0; i < 16; ++i) xv[i] = xr[lane + 32 * i];
        float gs[12];
#pragma unroll
        for (int e = 0; e < 12; ++e) {
            float acc = 0.f;
#pragma unroll
            for (int i = 0; i < 16; ++i)
                acc = fmaf(xv[i], Wgs[(size_t)(lane + 32 * i) * 12 + e], acc);
#pragma unroll
            for (int o = 16; o; o >>= 1) acc += __shfl_xor_sync(0xffffffffu, acc, o);
            gs[e] = acc + bgs[e];
        }
        float m = gs[0];
#pragma unroll
        for (int e = 1; e < 12; ++e) m = fmaxf(m, gs[e]);
        float s = 0.f;
#pragma unroll
        for (int e = 0; e < 12; ++e) { gs[e] = __expf(gs[e] - m); s += gs[e]; }
        const float inv = 1.f / s;
        if (lane == 0) {
#pragma unroll
            for (int e = 0; e < 12; ++e)
                g_gsw[(size_t)b * 12 + e] = gs[e] * inv;
        }
    }
}

// ============================================================================
// Tensor-core GEMM: A loaded as RAW f32 from x, split to bf16 hi/lo in
// registers between LDS and MMA (fma/alu pipes are idle; same DRAM bytes).
// B pre-split bf16 hi/lo via ldmatrix.trans. 3-product accumulation.
// CTA tile 128x128, BK=32, 3-stage cp.async, 2 CTAs/SM.
// A smem: 128 rows x 32 f32, row stride 160B (==8 floats mod 32 -> lds.64
// conflict-free per half-warp).
// ============================================================================
#define OFF_A   0
#define A_STRIDE 160
#define OFF_BHI 20480
#define OFF_BLO 28672
#define STG     36864
#define GEMM_SMEM (3 * STG)   // 110592

__device__ __forceinline__ void issue_chunk(
    uint32_t sm32, int stage, int c0,
    const float* __restrict__ xz,
    const __nv_bfloat16* __restrict__ whi, const __nv_bfloat16* __restrict__ wlo,
    int m0, int n0, int tid)
{
    const uint32_t sa = sm32 + stage * STG;
    // A: 128 rows x 32 f32 (128B data per 160B row)
#pragma unroll
    for (int i = 0; i < 4; ++i) {
        const int idx = tid + i * 256;
        const int m = idx >> 3, u = idx & 7;
        const float* src = xz + (size_t)(m0 + m) * DIN + c0 + u * 4;
        cpasync16(sa + OFF_A + m * A_STRIDE + u * 16, src);
    }
    // B: 32 k-rows x 128n hi/lo, XOR-swizzled 16B units
#pragma unroll
    for (int i = 0; i < 2; ++i) {
        const int idx = tid + i * 256;
        const int k = idx >> 4, u = idx & 15;
        const size_t go = (size_t)(c0 + k) * HDIM + n0 + u * 8;
        const uint32_t phys = (u & 8) | ((u & 7) ^ (k & 7));
        const uint32_t d = sa + OFF_BHI + k * 256 + phys * 16;
        cpasync16(d, whi + go);
        cpasync16(d + (OFF_BLO - OFF_BHI), wlo + go);
    }
}

__global__ void __launch_bounds__(256, 2)
gemm_tc(const float* __restrict__ x,
        const float* __restrict__ bspec, const float* __restrict__ bsh)
{
    extern __shared__ char smem[];
    const uint32_t sm32 = smem_u32(smem);
    const int tid  = threadIdx.x;
    const int wid  = tid >> 5;
    const int lane = tid & 31;
    const int wm0  = (wid & 3) * 32;
    const int wn0  = (wid >> 2) * 64;

    const int n0 = blockIdx.x * 128;
    const int m0 = blockIdx.y * 128;
    const int z  = blockIdx.z;

    const int zsel = (z < 8) ? (z >> 1) : 4;
    const float* xz = x + (size_t)zsel * BATCH * DIN;
    const __nv_bfloat16* whi = g_whi + (size_t)z * DIN * HDIM;
    const __nv_bfloat16* wlo = g_wlo + (size_t)z * DIN * HDIM;
    const float* bias = (z < 8) ? (bspec + z * HDIM) : (bsh + (z - 8) * HDIM);
    float* outp = (z < 8) ? (g_spec + (size_t)z * BATCH * HDIM)
                          : (g_shared + (size_t)(z - 8) * BATCH * HDIM);

    float acc[2][8][4];
#pragma unroll
    for (int f = 0; f < 2; ++f)
#pragma unroll
        for (int j = 0; j < 8; ++j)
#pragma unroll
            for (int q = 0; q < 4; ++q) acc[f][j][q] = 0.f;

    // prologue: 2 stages in flight
#pragma unroll
    for (int p = 0; p < 2; ++p) {
        issue_chunk(sm32, p, p * 32, xz, whi, wlo, m0, n0, tid);
        CP_COMMIT();
    }

    for (int kt = 0; kt < 16; ++kt) {
        CP_WAIT1();
        __syncthreads();

        if (kt + 2 < 16)
            issue_chunk(sm32, (kt + 2) % 3, (kt + 2) * 32, xz, whi, wlo, m0, n0, tid);
        CP_COMMIT();

        const uint32_t sa = sm32 + (kt % 3) * STG;
        const char* sp = smem + (kt % 3) * STG;
#pragma unroll
        for (int ksb = 0; ksb < 2; ++ksb) {
            const int kb = ksb * 16;
            // ---- A fragments: lds.64 f32 pairs -> register split to bf16 hi/lo
            uint32_t ah[2][4], al[2][4];
#pragma unroll
            for (int f = 0; f < 2; ++f) {
                const char* ap = sp + OFF_A
                    + (wm0 + f * 16 + (lane >> 2)) * A_STRIDE
                    + (kb + ((lane & 3) << 1)) * 4;
                const float2 v0 = *(const float2*)(ap);
                const float2 v1 = *(const float2*)(ap + 8 * A_STRIDE);
                const float2 v2 = *(const float2*)(ap + 32);
                const float2 v3 = *(const float2*)(ap + 8 * A_STRIDE + 32);
                split2(v0.x, v0.y, ah[f][0], al[f][0]);
                split2(v1.x, v1.y, ah[f][1], al[f][1]);
                split2(v2.x, v2.y, ah[f][2], al[f][2]);
                split2(v3.x, v3.y, ah[f][3], al[f][3]);
            }
            const int g = lane >> 3, r = lane & 7;
            const int krow = kb + (g & 1) * 8 + r;
#pragma unroll
            for (int c = 0; c < 4; ++c) {
                const int noff = wn0 + c * 16 + (g >> 1) * 8;
                const uint32_t u = (uint32_t)(noff >> 3);
                const uint32_t phys = (u & 8) | ((u & 7) ^ (uint32_t)(krow & 7));
                const uint32_t baddr = sa + OFF_BHI + krow * 256 + phys * 16;
                uint32_t bh[4], bl[4];
                ldsm4t(bh[0], bh[1], bh[2], bh[3], baddr);
                ldsm4t(bl[0], bl[1], bl[2], bl[3], baddr + (OFF_BLO - OFF_BHI));
#pragma unroll
                for (int f = 0; f < 2; ++f) {
#pragma unroll
                    for (int jj = 0; jj < 2; ++jj) {
                        float* d = acc[f][2 * c + jj];
                        mma16816(d, ah[f], bh[2 * jj], bh[2 * jj + 1]);
                        mma16816(d, ah[f], bl[2 * jj], bl[2 * jj + 1]);
                        mma16816(d, al[f], bh[2 * jj], bh[2 * jj + 1]);
                    }
                }
            }
        }
    }

    // epilogue: bias + relu, direct global stores
#pragma unroll
    for (int f = 0; f < 2; ++f) {
#pragma unroll
        for (int j = 0; j < 8; ++j) {
            const int row = m0 + wm0 + f * 16 + (lane >> 2);
            const int col = n0 + wn0 + j * 8 + (lane & 3) * 2;
            const float b0 = __ldg(&bias[col]);
            const float b1 = __ldg(&bias[col + 1]);
            float2 v0, v1;
            v0.x = fmaxf(acc[f][j][0] + b0, 0.f);
            v0.y = fmaxf(acc[f][j][1] + b1, 0.f);
            v1.x = fmaxf(acc[f][j][2] + b0, 0.f);
            v1.y = fmaxf(acc[f][j][3] + b1, 0.f);
            *(float2*)(outp + (size_t)row * HDIM + col)       = v0;
            *(float2*)(outp + (size_t)(row + 8) * HDIM + col) = v1;
        }
    }
}

// ============================================================================
// Combine: 4 rows per block, float4 per thread, no transcendentals.
// ============================================================================
__global__ __launch_bounds__(256)
void combine_kernel(float* __restrict__ out)
{
    __shared__ float w[4][36];
    const int b0  = blockIdx.x * 4;
    const int tid = threadIdx.x;
    if (tid < 144) {
        const int row = tid / 36, e = tid % 36;
        float v;
        if (e < 24) v = g_gw[((size_t)(e / 6) * BATCH + b0 + row) * 6 + (e % 6)];
        else        v = g_gsw[(size_t)(b0 + row) * 12 + (e - 24)];
        w[row][e] = v;
    }
    __syncthreads();

    const int r = tid >> 6;
    const int b = b0 + r;
    const int h = (tid & 63) * 4;

    float4 sp[8];
#pragma unroll
    for (int j = 0; j < 8; ++j)
        sp[j] = *(const float4*)&g_spec[((size_t)j * BATCH + b) * HDIM + h];
    float4 sh[4];
#pragma unroll
    for (int e = 0; e < 4; ++e)
        sh[e] = *(const float4*)&g_shared[((size_t)e * BATCH + b) * HDIM + h];

    {
        float4 o = make_float4(0.f, 0.f, 0.f, 0.f);
#pragma unroll
        for (int j = 0; j < 8; ++j) {
            const float ww = w[r][24 + j];
            o.x = fmaf(ww, sp[j].x, o.x); o.y = fmaf(ww, sp[j].y, o.y);
            o.z = fmaf(ww, sp[j].z, o.z); o.w = fmaf(ww, sp[j].w, o.w);
        }
#pragma unroll
        for (int e = 0; e < 4; ++e) {
            const float ww = w[r][32 + e];
            o.x = fmaf(ww, sh[e].x, o.x); o.y = fmaf(ww, sh[e].y, o.y);
            o.z = fmaf(ww, sh[e].z, o.z); o.w = fmaf(ww, sh[e].w, o.w);
        }
        *(float4*)&out[((size_t)4 * BATCH + b) * HDIM + h] = o;
    }

#pragma unroll
    for (int n = 0; n < 4; ++n) {
        float4 o = make_float4(0.f, 0.f, 0.f, 0.f);
        const float w0 = w[r][n * 6 + 0], w1 = w[r][n * 6 + 1];
        o.x = w0 * sp[2 * n].x + w1 * sp[2 * n + 1].x;
        o.y = w0 * sp[2 * n].y + w1 * sp[2 * n + 1].y;
        o.z = w0 * sp[2 * n].z + w1 * sp[2 * n + 1].z;
        o.w = w0 * sp[2 * n].w + w1 * sp[2 * n + 1].w;
#pragma unroll
        for (int e = 0; e < 4; ++e) {
            const float ww = w[r][n * 6 + 2 + e];
            o.x = fmaf(ww, sh[e].x, o.x); o.y = fmaf(ww, sh[e].y, o.y);
            o.z = fmaf(ww, sh[e].z, o.z); o.w = fmaf(ww, sh[e].w, o.w);
        }
        *(float4*)&out[((size_t)n * BATCH + b) * HDIM + h] = o;
    }
}

// ============================================================================
extern "C" void kernel_launch(void* const* d_in, const int* in_sizes, int n_in,
                              void* d_out, int out_size)
{
    const float* x     = (const float*)d_in[0];
    const int*   sim   = (const int*)d_in[1];
    const float* Wspec = (const float*)d_in[2];
    const float* bspec = (const float*)d_in[3];
    const float* Wsh   = (const float*)d_in[4];
    const float* bsh   = (const float*)d_in[5];
    const float* Wg    = (const float*)d_in[6];
    const float* bg    = (const float*)d_in[7];
    const float* Wgs   = (const float*)d_in[8];
    const float* bgs   = (const float*)d_in[9];
    float* out = (float*)d_out;

    split_w_kernel<<<WSBLK + WHBLK, 256>>>((const float4*)Wspec, (const float4*)Wsh);

    gates_kernel<<<BATCH / 8, 256>>>(x, Wg, bg, Wgs, bgs, sim);

    cudaFuncSetAttribute(gemm_tc, cudaFuncAttributeMaxDynamicSharedMemorySize, GEMM_SMEM);
    dim3 gemm_grid(2, 128, 12);
    gemm_tc<<<gemm_grid, 256, GEMM_SMEM>>>(x, bspec, bsh);

    combine_kernel<<<BATCH / 4, 256>>>(out);
}

// round 11
// speedup vs baseline: 1.6038x; 1.0425x over previous
#include <cuda_runtime.h>
#include <cuda_bf16.h>
#include <math.h>
#include <stdint.h>

#define BATCH 16384
#define DIN   512
#define HDIM  256

// -------- scratch (static device allocations; no cudaMalloc allowed) --------
__device__ float g_spec[8 * BATCH * HDIM];            // [z][b][h]
__device__ float g_shared[4 * BATCH * HDIM];          // [e][b][h]
__device__ float g_gw[4 * BATCH * 6];                 // FINAL domain gate weights
__device__ float g_gsw[BATCH * 12];                   // FINAL shared gate weights
__device__ __nv_bfloat16 g_whi[12 * DIN * HDIM];      // [z][k][n]
__device__ __nv_bfloat16 g_wlo[12 * DIN * HDIM];

// ============================================================================
// helpers
// ============================================================================
__device__ __forceinline__ uint32_t smem_u32(const void* p) {
    uint32_t a;
    asm("{ .reg .u64 t; cvta.to.shared.u64 t, %1; cvt.u32.u64 %0, t; }" : "=r"(a) : "l"(p));
    return a;
}
__device__ __forceinline__ void cpasync16(uint32_t dst, const void* src) {
    asm volatile("cp.async.cg.shared.global [%0], [%1], 16;" :: "r"(dst), "l"(src) : "memory");
}
#define CP_COMMIT() asm volatile("cp.async.commit_group;" ::: "memory")
#define CP_WAIT1()  asm volatile("cp.async.wait_group 1;" ::: "memory")

__device__ __forceinline__ void ldsm4t(uint32_t& r0, uint32_t& r1, uint32_t& r2, uint32_t& r3, uint32_t addr) {
    asm volatile("ldmatrix.sync.aligned.m8n8.x4.trans.shared.b16 {%0,%1,%2,%3}, [%4];"
                 : "=r"(r0), "=r"(r1), "=r"(r2), "=r"(r3) : "r"(addr));
}
__device__ __forceinline__ void mma16816(float* d, const uint32_t* a, uint32_t b0, uint32_t b1) {
    asm volatile(
        "mma.sync.aligned.m16n8k16.row.col.f32.bf16.bf16.f32 "
        "{%0,%1,%2,%3}, {%4,%5,%6,%7}, {%8,%9}, {%0,%1,%2,%3};"
        : "+f"(d[0]), "+f"(d[1]), "+f"(d[2]), "+f"(d[3])
        : "r"(a[0]), "r"(a[1]), "r"(a[2]), "r"(a[3]), "r"(b0), "r"(b1));
}

// Fast hi/lo bf16 split: 2 packed cvts + 2 bit-ops + 2 subs.
// cvt.rn.bf16x2.f32 rounds identically to __float2bfloat16 (cvt.rn.bf16.f32),
// so results are bit-identical to the scalar version.
__device__ __forceinline__ void split2(float a0, float a1, uint32_t& hi, uint32_t& lo) {
    uint32_t h;
    asm("cvt.rn.bf16x2.f32 %0, %1, %2;" : "=r"(h) : "f"(a1), "f"(a0));
    const float h0f = __uint_as_float(h << 16);
    const float h1f = __uint_as_float(h & 0xffff0000u);
    const float l0 = a0 - h0f;
    const float l1 = a1 - h1f;
    uint32_t l;
    asm("cvt.rn.bf16x2.f32 %0, %1, %2;" : "=r"(l) : "f"(l1), "f"(l0));
    hi = h; lo = l;
}

// ============================================================================
// Fused prep kernel: blocks [0, WSBLK+WHBLK) split the weights to bf16 hi/lo;
// blocks [WSBLK+WHBLK, +NGATE) compute final gate weights (both softmaxes +
// sim mask). Both are small and independent; one launch, they overlap.
// ============================================================================
#define NWS4 (8 * DIN * HDIM / 4)           // 262144 float4
#define NWH4 (4 * DIN * HDIM / 4)           // 131072
#define WSBLK   (NWS4 / 1024)               // 256
#define WHBLK   (NWH4 / 1024)               // 128
#define WBLOCKS (WSBLK + WHBLK)             // 384
#define NGATE   (BATCH / 8)                 // 2048

__global__ __launch_bounds__(256)
void prep_kernel(const float4* __restrict__ Ws, const float4* __restrict__ Wh,
                 const float* __restrict__ x,
                 const float* __restrict__ Wg,  const float* __restrict__ bg,
                 const float* __restrict__ Wgs, const float* __restrict__ bgs,
                 const int* __restrict__ sim)
{
    if (blockIdx.x < WBLOCKS) {
        // ---- weight split path ----
        const float4* src;
        size_t dst0;
        if (blockIdx.x < WSBLK) {
            src  = Ws + (size_t)blockIdx.x * 1024;
            dst0 = (size_t)blockIdx.x * 1024;
        } else {
            src  = Wh + (size_t)(blockIdx.x - WSBLK) * 1024;
            dst0 = (size_t)NWS4 + (size_t)(blockIdx.x - WSBLK) * 1024;
        }
        const int t = threadIdx.x;
        float4 v0 = src[t];
        float4 v1 = src[t + 256];
        float4 v2 = src[t + 512];
        float4 v3 = src[t + 768];
        uint2* dh = (uint2*)g_whi;
        uint2* dl = (uint2*)g_wlo;
        uint32_t ha, la, hb, lb;
        split2(v0.x, v0.y, ha, la); split2(v0.z, v0.w, hb, lb);
        dh[dst0 + t]       = make_uint2(ha, hb); dl[dst0 + t]       = make_uint2(la, lb);
        split2(v1.x, v1.y, ha, la); split2(v1.z, v1.w, hb, lb);
        dh[dst0 + t + 256] = make_uint2(ha, hb); dl[dst0 + t + 256] = make_uint2(la, lb);
        split2(v2.x, v2.y, ha, la); split2(v2.z, v2.w, hb, lb);
        dh[dst0 + t + 512] = make_uint2(ha, hb); dl[dst0 + t + 512] = make_uint2(la, lb);
        split2(v3.x, v3.y, ha, la); split2(v3.z, v3.w, hb, lb);
        dh[dst0 + t + 768] = make_uint2(ha, hb); dl[dst0 + t + 768] = make_uint2(la, lb);
        return;
    }

    // ---- gates path ----
    const int b    = (blockIdx.x - WBLOCKS) * 8 + (threadIdx.x >> 5);
    const int lane = threadIdx.x & 31;

#pragma unroll
    for (int n = 0; n < 4; ++n) {
        const float* xr = x + ((size_t)n * BATCH + b) * DIN;
        float xv[16];
#pragma unroll
        for (int i = 0; i < 16; ++i) xv[i] = xr[lane + 32 * i];
        float zz[6];
#pragma unroll
        for (int e = 0; e < 6; ++e) {
            float acc = 0.f;
#pragma unroll
            for (int i = 0; i < 16; ++i)
                acc = fmaf(xv[i], Wg[(size_t)n * DIN * 6 + (size_t)(lane + 32 * i) * 6 + e], acc);
#pragma unroll
            for (int o = 16; o; o >>= 1) acc += __shfl_xor_sync(0xffffffffu, acc, o);
            zz[e] = acc + bg[n * 6 + e];
        }
        float m1 = zz[0];
#pragma unroll
        for (int e = 1; e < 6; ++e) m1 = fmaxf(m1, zz[e]);
        float s1 = 0.f;
#pragma unroll
        for (int e = 0; e < 6; ++e) { zz[e] = __expf(zz[e] - m1); s1 += zz[e]; }
        const float inv1 = 1.f / s1;
#pragma unroll
        for (int e = 0; e < 6; ++e) zz[e] *= inv1;

        const int s0 = sim[n * 2], s1i = sim[n * 2 + 1];
        bool valid[6];
        valid[0] = true; valid[1] = true;
#pragma unroll
        for (int e = 0; e < 4; ++e) valid[2 + e] = (s0 == e) || (s1i == e);
        float m2 = -1e30f;
#pragma unroll
        for (int e = 0; e < 6; ++e) if (valid[e]) m2 = fmaxf(m2, zz[e]);
        float w[6]; float s2 = 0.f;
#pragma unroll
        for (int e = 0; e < 6; ++e) { w[e] = valid[e] ? __expf(zz[e] - m2) : 0.f; s2 += w[e]; }
        const float inv2 = 1.f / s2;
        if (lane == 0) {
#pragma unroll
            for (int e = 0; e < 6; ++e)
                g_gw[((size_t)n * BATCH + b) * 6 + e] = w[e] * inv2;
        }
    }
    {
        const float* xr = x + ((size_t)4 * BATCH + b) * DIN;
        float xv[16];
#pragma unroll
        for (int i = 0; i < 16; ++i) xv[i] = xr[lane + 32 * i];
        float gs[12];
#pragma unroll
        for (int e = 0; e < 12; ++e) {
            float acc = 0.f;
#pragma unroll
            for (int i = 0; i < 16; ++i)
                acc = fmaf(xv[i], Wgs[(size_t)(lane + 32 * i) * 12 + e], acc);
#pragma unroll
            for (int o = 16; o; o >>= 1) acc += __shfl_xor_sync(0xffffffffu, acc, o);
            gs[e] = acc + bgs[e];
        }
        float m = gs[0];
#pragma unroll
        for (int e = 1; e < 12; ++e) m = fmaxf(m, gs[e]);
        float s = 0.f;
#pragma unroll
        for (int e = 0; e < 12; ++e) { gs[e] = __expf(gs[e] - m); s += gs[e]; }
        const float inv = 1.f / s;
        if (lane == 0) {
#pragma unroll
            for (int e = 0; e < 12; ++e)
                g_gsw[(size_t)b * 12 + e] = gs[e] * inv;
        }
    }
}

// ============================================================================
// Tensor-core GEMM: A loaded as raw f32, split to bf16 hi/lo in registers
// (packed cvt.bf16x2 path). B pre-split bf16 hi/lo via ldmatrix.trans.
// 3-product accumulation. CTA tile 128x128, BK=32, 3-stage cp.async, 2 CTA/SM.
// ============================================================================
#define OFF_A   0
#define A_STRIDE 160
#define OFF_BHI 20480
#define OFF_BLO 28672
#define STG     36864
#define GEMM_SMEM (3 * STG)   // 110592

__device__ __forceinline__ void issue_chunk(
    uint32_t sm32, int stage, int c0,
    const float* __restrict__ xz,
    const __nv_bfloat16* __restrict__ whi, const __nv_bfloat16* __restrict__ wlo,
    int m0, int n0, int tid)
{
    const uint32_t sa = sm32 + stage * STG;
    // A: 128 rows x 32 f32 (128B data per 160B row)
#pragma unroll
    for (int i = 0; i < 4; ++i) {
        const int idx = tid + i * 256;
        const int m = idx >> 3, u = idx & 7;
        const float* src = xz + (size_t)(m0 + m) * DIN + c0 + u * 4;
        cpasync16(sa + OFF_A + m * A_STRIDE + u * 16, src);
    }
    // B: 32 k-rows x 128n hi/lo, XOR-swizzled 16B units
#pragma unroll
    for (int i = 0; i < 2; ++i) {
        const int idx = tid + i * 256;
        const int k = idx >> 4, u = idx & 15;
        const size_t go = (size_t)(c0 + k) * HDIM + n0 + u * 8;
        const uint32_t phys = (u & 8) | ((u & 7) ^ (k & 7));
        const uint32_t d = sa + OFF_BHI + k * 256 + phys * 16;
        cpasync16(d, whi + go);
        cpasync16(d + (OFF_BLO - OFF_BHI), wlo + go);
    }
}

__global__ void __launch_bounds__(256, 2)
gemm_tc(const float* __restrict__ x,
        const float* __restrict__ bspec, const float* __restrict__ bsh)
{
    extern __shared__ char smem[];
    const uint32_t sm32 = smem_u32(smem);
    const int tid  = threadIdx.x;
    const int wid  = tid >> 5;
    const int lane = tid & 31;
    const int wm0  = (wid & 3) * 32;
    const int wn0  = (wid >> 2) * 64;

    const int n0 = blockIdx.x * 128;
    const int m0 = blockIdx.y * 128;
    const int z  = blockIdx.z;

    const int zsel = (z < 8) ? (z >> 1) : 4;
    const float* xz = x + (size_t)zsel * BATCH * DIN;
    const __nv_bfloat16* whi = g_whi + (size_t)z * DIN * HDIM;
    const __nv_bfloat16* wlo = g_wlo + (size_t)z * DIN * HDIM;
    const float* bias = (z < 8) ? (bspec + z * HDIM) : (bsh + (z - 8) * HDIM);
    float* outp = (z < 8) ? (g_spec + (size_t)z * BATCH * HDIM)
                          : (g_shared + (size_t)(z - 8) * BATCH * HDIM);

    float acc[2][8][4];
#pragma unroll
    for (int f = 0; f < 2; ++f)
#pragma unroll
        for (int j = 0; j < 8; ++j)
#pragma unroll
            for (int q = 0; q < 4; ++q) acc[f][j][q] = 0.f;

    // prologue: 2 stages in flight
#pragma unroll
    for (int p = 0; p < 2; ++p) {
        issue_chunk(sm32, p, p * 32, xz, whi, wlo, m0, n0, tid);
        CP_COMMIT();
    }

    for (int kt = 0; kt < 16; ++kt) {
        CP_WAIT1();
        __syncthreads();

        if (kt + 2 < 16)
            issue_chunk(sm32, (kt + 2) % 3, (kt + 2) * 32, xz, whi, wlo, m0, n0, tid);
        CP_COMMIT();

        const uint32_t sa = sm32 + (kt % 3) * STG;
        const char* sp = smem + (kt % 3) * STG;
#pragma unroll
        for (int ksb = 0; ksb < 2; ++ksb) {
            const int kb = ksb * 16;
            // ---- A fragments: lds.64 f32 pairs -> packed-cvt split to hi/lo
            uint32_t ah[2][4], al[2][4];
#pragma unroll
            for (int f = 0; f < 2; ++f) {
                const char* ap = sp + OFF_A
                    + (wm0 + f * 16 + (lane >> 2)) * A_STRIDE
                    + (kb + ((lane & 3) << 1)) * 4;
                const float2 v0 = *(const float2*)(ap);
                const float2 v1 = *(const float2*)(ap + 8 * A_STRIDE);
                const float2 v2 = *(const float2*)(ap + 32);
                const float2 v3 = *(const float2*)(ap + 8 * A_STRIDE + 32);
                split2(v0.x, v0.y, ah[f][0], al[f][0]);
                split2(v1.x, v1.y, ah[f][1], al[f][1]);
                split2(v2.x, v2.y, ah[f][2], al[f][2]);
                split2(v3.x, v3.y, ah[f][3], al[f][3]);
            }
            const int g = lane >> 3, r = lane & 7;
            const int krow = kb + (g & 1) * 8 + r;
#pragma unroll
            for (int c = 0; c < 4; ++c) {
                const int noff = wn0 + c * 16 + (g >> 1) * 8;
                const uint32_t u = (uint32_t)(noff >> 3);
                const uint32_t phys = (u & 8) | ((u & 7) ^ (uint32_t)(krow & 7));
                const uint32_t baddr = sa + OFF_BHI + krow * 256 + phys * 16;
                uint32_t bh[4], bl[4];
                ldsm4t(bh[0], bh[1], bh[2], bh[3], baddr);
                ldsm4t(bl[0], bl[1], bl[2], bl[3], baddr + (OFF_BLO - OFF_BHI));
#pragma unroll
                for (int f = 0; f < 2; ++f) {
#pragma unroll
                    for (int jj = 0; jj < 2; ++jj) {
                        float* d = acc[f][2 * c + jj];
                        mma16816(d, ah[f], bh[2 * jj], bh[2 * jj + 1]);
                        mma16816(d, ah[f], bl[2 * jj], bl[2 * jj + 1]);
                        mma16816(d, al[f], bh[2 * jj], bh[2 * jj + 1]);
                    }
                }
            }
        }
    }

    // epilogue: bias + relu, direct global stores
#pragma unroll
    for (int f = 0; f < 2; ++f) {
#pragma unroll
        for (int j = 0; j < 8; ++j) {
            const int row = m0 + wm0 + f * 16 + (lane >> 2);
            const int col = n0 + wn0 + j * 8 + (lane & 3) * 2;
            const float b0 = __ldg(&bias[col]);
            const float b1 = __ldg(&bias[col + 1]);
            float2 v0, v1;
            v0.x = fmaxf(acc[f][j][0] + b0, 0.f);
            v0.y = fmaxf(acc[f][j][1] + b1, 0.f);
            v1.x = fmaxf(acc[f][j][2] + b0, 0.f);
            v1.y = fmaxf(acc[f][j][3] + b1, 0.f);
            *(float2*)(outp + (size_t)row * HDIM + col)       = v0;
            *(float2*)(outp + (size_t)(row + 8) * HDIM + col) = v1;
        }
    }
}

// ============================================================================
// Combine: 4 rows per block, float4 per thread, no transcendentals.
// ============================================================================
__global__ __launch_bounds__(256)
void combine_kernel(float* __restrict__ out)
{
    __shared__ float w[4][36];
    const int b0  = blockIdx.x * 4;
    const int tid = threadIdx.x;
    if (tid < 144) {
        const int row = tid / 36, e = tid % 36;
        float v;
        if (e < 24) v = g_gw[((size_t)(e / 6) * BATCH + b0 + row) * 6 + (e % 6)];
        else        v = g_gsw[(size_t)(b0 + row) * 12 + (e - 24)];
        w[row][e] = v;
    }
    __syncthreads();

    const int r = tid >> 6;
    const int b = b0 + r;
    const int h = (tid & 63) * 4;

    float4 sp[8];
#pragma unroll
    for (int j = 0; j < 8; ++j)
        sp[j] = *(const float4*)&g_spec[((size_t)j * BATCH + b) * HDIM + h];
    float4 sh[4];
#pragma unroll
    for (int e = 0; e < 4; ++e)
        sh[e] = *(const float4*)&g_shared[((size_t)e * BATCH + b) * HDIM + h];

    {
        float4 o = make_float4(0.f, 0.f, 0.f, 0.f);
#pragma unroll
        for (int j = 0; j < 8; ++j) {
            const float ww = w[r][24 + j];
            o.x = fmaf(ww, sp[j].x, o.x); o.y = fmaf(ww, sp[j].y, o.y);
            o.z = fmaf(ww, sp[j].z, o.z); o.w = fmaf(ww, sp[j].w, o.w);
        }
#pragma unroll
        for (int e = 0; e < 4; ++e) {
            const float ww = w[r][32 + e];
            o.x = fmaf(ww, sh[e].x, o.x); o.y = fmaf(ww, sh[e].y, o.y);
            o.z = fmaf(ww, sh[e].z, o.z); o.w = fmaf(ww, sh[e].w, o.w);
        }
        *(float4*)&out[((size_t)4 * BATCH + b) * HDIM + h] = o;
    }

#pragma unroll
    for (int n = 0; n < 4; ++n) {
        float4 o = make_float4(0.f, 0.f, 0.f, 0.f);
        const float w0 = w[r][n * 6 + 0], w1 = w[r][n * 6 + 1];
        o.x = w0 * sp[2 * n].x + w1 * sp[2 * n + 1].x;
        o.y = w0 * sp[2 * n].y + w1 * sp[2 * n + 1].y;
        o.z = w0 * sp[2 * n].z + w1 * sp[2 * n + 1].z;
        o.w = w0 * sp[2 * n].w + w1 * sp[2 * n + 1].w;
#pragma unroll
        for (int e = 0; e < 4; ++e) {
            const float ww = w[r][n * 6 + 2 + e];
            o.x = fmaf(ww, sh[e].x, o.x); o.y = fmaf(ww, sh[e].y, o.y);
            o.z = fmaf(ww, sh[e].z, o.z); o.w = fmaf(ww, sh[e].w, o.w);
        }
        *(float4*)&out[((size_t)n * BATCH + b) * HDIM + h] = o;
    }
}

// ============================================================================
extern "C" void kernel_launch(void* const* d_in, const int* in_sizes, int n_in,
                              void* d_out, int out_size)
{
    const float* x     = (const float*)d_in[0];
    const int*   sim   = (const int*)d_in[1];
    const float* Wspec = (const float*)d_in[2];
    const float* bspec = (const float*)d_in[3];
    const float* Wsh   = (const float*)d_in[4];
    const float* bsh   = (const float*)d_in[5];
    const float* Wg    = (const float*)d_in[6];
    const float* bg    = (const float*)d_in[7];
    const float* Wgs   = (const float*)d_in[8];
    const float* bgs   = (const float*)d_in[9];
    float* out = (float*)d_out;

    prep_kernel<<<WBLOCKS + NGATE, 256>>>(
        (const float4*)Wspec, (const float4*)Wsh,
        x, Wg, bg, Wgs, bgs, sim);

    cudaFuncSetAttribute(gemm_tc, cudaFuncAttributeMaxDynamicSharedMemorySize, GEMM_SMEM);
    dim3 gemm_grid(2, 128, 12);
    gemm_tc<<<gemm_grid, 256, GEMM_SMEM>>>(x, bspec, bsh);

    combine_kernel<<<BATCH / 4, 256>>>(out);
}